// round 5
// baseline (speedup 1.0000x reference)
#include <cuda_runtime.h>
#include <cuda_bf16.h>
#include <math.h>
#include <stdint.h>

// ---------------------------------------------------------------- constants
#define NTOK   8192
#define HIDDEN 2048
#define NEXP   8
#define TOPK   2
#define M_TOT  (NTOK * TOPK)      // 16384
#define CAP    (M_TOT / NEXP)     // 2048
#define KDIM   2048
#define NDIM   2048

constexpr int BM = 128, BN = 64, BK = 64;       // int8: BK in bytes == elements
constexpr int NS = 3;
constexpr int NITER = KDIM / BK;                // 32
constexpr uint32_t A_T = 128 * 64;              // 8 KB per A term tile
constexpr uint32_t B_T = 64 * 64;               // 4 KB per B term tile
constexpr uint32_t OFF_A1 = 0, OFF_A2 = A_T, OFF_B1 = 2 * A_T, OFF_B2 = 2 * A_T + B_T;
constexpr uint32_t STAGE = 2 * A_T + 2 * B_T;   // 24 KB
constexpr uint32_t SMEM_SZ = NS * STAGE;        // 72 KB

constexpr float SH    = 127.0f / 6.0f;          // static scale for gelu(h)
constexpr float SHINV = 6.0f / 127.0f;

// ---------------------------------------------------------------- scratch
__device__ __align__(1024) int8_t g_x1[(size_t)M_TOT * KDIM];
__device__ __align__(1024) int8_t g_x2[(size_t)M_TOT * KDIM];
__device__ float  g_xs[M_TOT];
__device__ __align__(1024) int8_t g_w1a[(size_t)NEXP * NDIM * KDIM];
__device__ __align__(1024) int8_t g_w1b[(size_t)NEXP * NDIM * KDIM];
__device__ float  g_w1s[NEXP * NDIM];
__device__ __align__(1024) int8_t g_w2a[(size_t)NEXP * NDIM * KDIM];
__device__ __align__(1024) int8_t g_w2b[(size_t)NEXP * NDIM * KDIM];
__device__ float  g_w2s[NEXP * NDIM];
__device__ __align__(1024) int8_t g_h1[(size_t)M_TOT * NDIM];
__device__ __align__(1024) int8_t g_h2[(size_t)M_TOT * NDIM];
__device__ __align__(1024) float  g_y[(size_t)M_TOT * HIDDEN];

// ---------------------------------------------------------------- helpers
__device__ __forceinline__ uint32_t smem_u32(const void* p) {
    uint32_t a;
    asm("{ .reg .u64 t; cvta.to.shared.u64 t, %1; cvt.u32.u64 %0, t; }"
        : "=r"(a) : "l"(p));
    return a;
}
__device__ __forceinline__ uint32_t sw128(uint32_t off) {
    return off ^ ((off >> 3) & 0x70);
}
__device__ __forceinline__ void cp16(uint32_t dst, const void* src) {
    asm volatile("cp.async.cg.shared.global [%0], [%1], 16;"
                 :: "r"(dst), "l"(src));
}
__device__ __forceinline__ void cp_commit() {
    asm volatile("cp.async.commit_group;");
}
template <int N>
__device__ __forceinline__ void cp_wait() {
    asm volatile("cp.async.wait_group %0;" :: "n"(N));
}
__device__ __forceinline__ void ldsm4(uint32_t* r, uint32_t addr) {
    asm volatile("ldmatrix.sync.aligned.m8n8.x4.shared.b16 {%0,%1,%2,%3}, [%4];"
                 : "=r"(r[0]), "=r"(r[1]), "=r"(r[2]), "=r"(r[3]) : "r"(addr));
}
__device__ __forceinline__ void imma(int* c, const uint32_t* a, const uint32_t* b) {
    asm volatile(
        "mma.sync.aligned.m16n8k32.row.col.s32.s8.s8.s32 "
        "{%0,%1,%2,%3},{%4,%5,%6,%7},{%8,%9},{%0,%1,%2,%3};"
        : "+r"(c[0]), "+r"(c[1]), "+r"(c[2]), "+r"(c[3])
        : "r"(a[0]), "r"(a[1]), "r"(a[2]), "r"(a[3]), "r"(b[0]), "r"(b[1]));
}
__device__ __forceinline__ int8_t clamp8(float t) {
    t = fminf(fmaxf(t, -127.0f), 127.0f);
    return (int8_t)__float2int_rn(t);
}

// ---------------------------------------------------------------- GEMM (int8)
// C[r,n] = sum_k A[r,k]*W[e,n,k], A=(A1+A2/254)*saInv, W=(B1+B2/254)*sbInv
// GELU=true: A scale per-row (As), output = gelu -> static-quant int8 pair.
// GELU=false: A scale static SHINV, output f32.
template <bool GELU>
__global__ void __launch_bounds__(256, 2)
gemm_i8(const int8_t* __restrict__ A1, const int8_t* __restrict__ A2,
        const float* __restrict__ As,
        const int8_t* __restrict__ B1, const int8_t* __restrict__ B2,
        const float* __restrict__ Bs,
        int8_t* __restrict__ oq1, int8_t* __restrict__ oq2,
        float* __restrict__ of32) {
    extern __shared__ __align__(1024) char smem[];
    const uint32_t sb = smem_u32(smem);
    const int tid  = threadIdx.x;
    const int lane = tid & 31;
    const int w    = tid >> 5;
    const int wm   = w & 3;        // 4 M quarters (32 rows)
    const int wn   = w >> 2;       // 2 N halves (32 cols)
    const int grow0 = blockIdx.y * BM;
    const int gcol0 = blockIdx.x * BN;
    const int e     = grow0 / CAP;

    // ---- loader: 6 x 16B per thread per stage
    const int lr = tid >> 2;             // 0..63
    const int lc = tid & 3;              // 16B chunk
    const uint32_t s_lo = sw128((uint32_t)lr * 64 + lc * 16);
    const uint32_t s_hi = sw128((uint32_t)(64 + lr) * 64 + lc * 16);
    const int8_t* a1r0 = A1 + (size_t)(grow0 + lr) * KDIM + lc * 16;
    const int8_t* a1r1 = A1 + (size_t)(grow0 + 64 + lr) * KDIM + lc * 16;
    const int8_t* a2r0 = A2 + (size_t)(grow0 + lr) * KDIM + lc * 16;
    const int8_t* a2r1 = A2 + (size_t)(grow0 + 64 + lr) * KDIM + lc * 16;
    const int8_t* b1p  = B1 + ((size_t)e * NDIM + gcol0 + lr) * KDIM + lc * 16;
    const int8_t* b2p  = B2 + ((size_t)e * NDIM + gcol0 + lr) * KDIM + lc * 16;

    auto load_stage = [&](int it) {
        if (it < NITER) {
            const uint32_t base = sb + (uint32_t)(it % NS) * STAGE;
            const int ko = it * BK;
            cp16(base + OFF_A1 + s_lo, a1r0 + ko);
            cp16(base + OFF_A1 + s_hi, a1r1 + ko);
            cp16(base + OFF_A2 + s_lo, a2r0 + ko);
            cp16(base + OFF_A2 + s_hi, a2r1 + ko);
            cp16(base + OFF_B1 + s_lo, b1p + ko);
            cp16(base + OFF_B2 + s_lo, b2p + ko);
        }
        cp_commit();
    };

    // ---- ldmatrix per-lane offsets (64B rows; byte pattern == bf16 k16 case)
    const int ar  = lane & 15;
    const int akh = lane >> 4;
    const uint32_t aoff = sw128((uint32_t)ar * 64 + akh * 16);
    const int brn = lane & 7;
    const int bh  = (lane >> 3) & 1;
    const int bgs = lane >> 4;
    const int nrow0 = wn * 32 + bgs * 8 + brn;
    const uint32_t boff0 = sw128((uint32_t)nrow0 * 64 + bh * 16);
    const uint32_t boff1 = sw128((uint32_t)(nrow0 + 16) * 64 + bh * 16);

    int accM[2][4][4], accX[2][4][4];
#pragma unroll
    for (int i = 0; i < 2; i++)
#pragma unroll
        for (int j = 0; j < 4; j++)
#pragma unroll
            for (int k = 0; k < 4; k++) { accM[i][j][k] = 0; accX[i][j][k] = 0; }

    load_stage(0);
    load_stage(1);

    for (int it = 0; it < NITER; it++) {
        cp_wait<1>();
        __syncthreads();
        load_stage(it + 2);

        const uint32_t base = sb + (uint32_t)(it % NS) * STAGE;
#pragma unroll
        for (int kk = 0; kk < 2; kk++) {
            const uint32_t kx = (uint32_t)kk << 5;
            uint32_t b1f[4][2], b2f[4][2];
            {
                uint32_t t0[4], t1[4];
                ldsm4(t0, base + OFF_B1 + (boff0 ^ kx));
                b1f[0][0] = t0[0]; b1f[0][1] = t0[1];
                b1f[1][0] = t0[2]; b1f[1][1] = t0[3];
                ldsm4(t1, base + OFF_B1 + (boff1 ^ kx));
                b1f[2][0] = t1[0]; b1f[2][1] = t1[1];
                b1f[3][0] = t1[2]; b1f[3][1] = t1[3];
                ldsm4(t0, base + OFF_B2 + (boff0 ^ kx));
                b2f[0][0] = t0[0]; b2f[0][1] = t0[1];
                b2f[1][0] = t0[2]; b2f[1][1] = t0[3];
                ldsm4(t1, base + OFF_B2 + (boff1 ^ kx));
                b2f[2][0] = t1[0]; b2f[2][1] = t1[1];
                b2f[3][0] = t1[2]; b2f[3][1] = t1[3];
            }
            const uint32_t aaddr = base + wm * 2048 + (aoff ^ kx);
#pragma unroll
            for (int mi = 0; mi < 2; mi++) {
                uint32_t a1f[4], a2f[4];
                ldsm4(a1f, aaddr + mi * 1024);
                ldsm4(a2f, aaddr + A_T + mi * 1024);
#pragma unroll
                for (int g = 0; g < 4; g++) {
                    imma(accM[mi][g], a1f, b1f[g]);
                    imma(accX[mi][g], a1f, b2f[g]);
                    imma(accX[mi][g], a2f, b1f[g]);
                }
            }
        }
    }

    // ---------------- epilogue
    const int r_in = lane >> 2;
    const int c_in = (lane & 3) * 2;
    float sa[2][2];
#pragma unroll
    for (int mi = 0; mi < 2; mi++)
#pragma unroll
        for (int half = 0; half < 2; half++) {
            const int row = grow0 + wm * 32 + mi * 16 + half * 8 + r_in;
            sa[mi][half] = GELU ? As[row] : SHINV;
        }
#pragma unroll
    for (int mi = 0; mi < 2; mi++) {
#pragma unroll
        for (int g = 0; g < 4; g++) {
            const int col = gcol0 + wn * 32 + g * 8 + c_in;
            const float2 sbv = *(const float2*)(Bs + (size_t)e * NDIM + col);
#pragma unroll
            for (int half = 0; half < 2; half++) {
                const int row = grow0 + wm * 32 + mi * 16 + half * 8 + r_in;
                const float comb0 = (float)accM[mi][g][half * 2 + 0] +
                                    (float)accX[mi][g][half * 2 + 0] * (1.0f / 254.0f);
                const float comb1 = (float)accM[mi][g][half * 2 + 1] +
                                    (float)accX[mi][g][half * 2 + 1] * (1.0f / 254.0f);
                float v0 = comb0 * (sa[mi][half] * sbv.x);
                float v1 = comb1 * (sa[mi][half] * sbv.y);
                const size_t off = (size_t)row * NDIM + col;
                if (GELU) {
                    v0 = 0.5f * v0 * (1.0f + erff(v0 * 0.70710678118654752f));
                    v1 = 0.5f * v1 * (1.0f + erff(v1 * 0.70710678118654752f));
                    const float t0 = v0 * SH, t1 = v1 * SH;
                    const float q0 = rintf(fminf(fmaxf(t0, -127.f), 127.f));
                    const float q1 = rintf(fminf(fmaxf(t1, -127.f), 127.f));
                    char2 c1, c2;
                    c1.x = (char)(int)q0;
                    c1.y = (char)(int)q1;
                    c2.x = clamp8((t0 - q0) * 254.0f);
                    c2.y = clamp8((t1 - q1) * 254.0f);
                    *(char2*)(oq1 + off) = c1;
                    *(char2*)(oq2 + off) = c2;
                } else {
                    *(float2*)(of32 + off) = make_float2(v0, v1);
                }
            }
        }
    }
}

// ---------------------------------------------------------------- quantization
// Per-row 2-term int8 quantization: v = sinv*(q1 + q2/254), sinv = rmax/127.
__device__ __forceinline__ void quant_row_body(const float* __restrict__ src,
                                               int8_t* __restrict__ q1,
                                               int8_t* __restrict__ q2,
                                               float* __restrict__ sinv_out) {
    const int tid = threadIdx.x;
    float v[8];
    float m = 0.0f;
#pragma unroll
    for (int i = 0; i < 8; i++) {
        v[i] = src[tid + i * 256];
        m = fmaxf(m, fabsf(v[i]));
    }
#pragma unroll
    for (int o = 16; o > 0; o >>= 1) m = fmaxf(m, __shfl_xor_sync(~0u, m, o));
    __shared__ float sm[8];
    if ((tid & 31) == 0) sm[tid >> 5] = m;
    __syncthreads();
    float rm = sm[0];
#pragma unroll
    for (int j = 1; j < 8; j++) rm = fmaxf(rm, sm[j]);
    rm = fmaxf(rm, 1e-30f);
    const float s = 127.0f / rm;
    if (tid == 0) *sinv_out = rm * (1.0f / 127.0f);
#pragma unroll
    for (int i = 0; i < 8; i++) {
        const float t  = v[i] * s;               // |t| <= 127
        const float t1 = rintf(t);
        q1[tid + i * 256] = (int8_t)(int)t1;
        q2[tid + i * 256] = (int8_t)__float2int_rn((t - t1) * 254.0f);
    }
}

__global__ void quant_rows(const float* __restrict__ in, int8_t* __restrict__ q1,
                           int8_t* __restrict__ q2, float* __restrict__ sinv) {
    const size_t row = blockIdx.x;
    quant_row_body(in + row * 2048, q1 + row * 2048, q2 + row * 2048, sinv + row);
}

__global__ void scatter_quant(const float* __restrict__ x, const int* __restrict__ scat,
                              int8_t* __restrict__ q1, int8_t* __restrict__ q2,
                              float* __restrict__ sinv) {
    const int p = blockIdx.x;                    // [0, M_TOT)
    const size_t d = (size_t)scat[p];
    quant_row_body(x + (size_t)(p >> 1) * HIDDEN, q1 + d * 2048, q2 + d * 2048,
                   sinv + d);
}

__global__ void combine_kernel(const int* __restrict__ scat, float* __restrict__ out) {
    const int idx = blockIdx.x * blockDim.x + threadIdx.x;   // NTOK * HIDDEN/4
    const int t  = idx / (HIDDEN / 4);
    const int c4 = (idx % (HIDDEN / 4)) * 4;
    const int s0 = scat[t * TOPK + 0];
    const int s1 = scat[t * TOPK + 1];
    float4 v0 = *(const float4*)(g_y + (size_t)s0 * HIDDEN + c4);
    float4 v1 = *(const float4*)(g_y + (size_t)s1 * HIDDEN + c4);
    *(float4*)(out + (size_t)t * HIDDEN + c4) =
        make_float4(v0.x + v1.x, v0.y + v1.y, v0.z + v1.z, v0.w + v1.w);
}

// ---------------------------------------------------------------- host
extern "C" void kernel_launch(void* const* d_in, const int* in_sizes, int n_in,
                              void* d_out, int out_size) {
    const float* x    = (const float*)d_in[0];
    const float* w1   = (const float*)d_in[1];
    const float* w2   = (const float*)d_in[2];
    const int*   scat = (const int*)d_in[3];
    float* out = (float*)d_out;

    void *x1, *x2, *xs, *w1a, *w1b, *w1s, *w2a, *w2b, *w2s, *h1, *h2, *y;
    cudaGetSymbolAddress(&x1, g_x1);   cudaGetSymbolAddress(&x2, g_x2);
    cudaGetSymbolAddress(&xs, g_xs);
    cudaGetSymbolAddress(&w1a, g_w1a); cudaGetSymbolAddress(&w1b, g_w1b);
    cudaGetSymbolAddress(&w1s, g_w1s);
    cudaGetSymbolAddress(&w2a, g_w2a); cudaGetSymbolAddress(&w2b, g_w2b);
    cudaGetSymbolAddress(&w2s, g_w2s);
    cudaGetSymbolAddress(&h1, g_h1);   cudaGetSymbolAddress(&h2, g_h2);
    cudaGetSymbolAddress(&y, g_y);

    cudaFuncSetAttribute(gemm_i8<true>,  cudaFuncAttributeMaxDynamicSharedMemorySize,
                         (int)SMEM_SZ);
    cudaFuncSetAttribute(gemm_i8<false>, cudaFuncAttributeMaxDynamicSharedMemorySize,
                         (int)SMEM_SZ);

    quant_rows<<<NEXP * NDIM, 256>>>(w1, (int8_t*)w1a, (int8_t*)w1b, (float*)w1s);
    quant_rows<<<NEXP * NDIM, 256>>>(w2, (int8_t*)w2a, (int8_t*)w2b, (float*)w2s);
    scatter_quant<<<M_TOT, 256>>>(x, scat, (int8_t*)x1, (int8_t*)x2, (float*)xs);

    // fc1: x @ w1^T -> gelu -> h (int8 2-term, static scale)
    gemm_i8<true><<<dim3(NDIM / BN, M_TOT / BM), 256, SMEM_SZ>>>(
        (const int8_t*)x1, (const int8_t*)x2, (const float*)xs,
        (const int8_t*)w1a, (const int8_t*)w1b, (const float*)w1s,
        (int8_t*)h1, (int8_t*)h2, nullptr);

    // fc2: h @ w2^T -> y (f32)
    gemm_i8<false><<<dim3(HIDDEN / BN, M_TOT / BM), 256, SMEM_SZ>>>(
        (const int8_t*)h1, (const int8_t*)h2, nullptr,
        (const int8_t*)w2a, (const int8_t*)w2b, (const float*)w2s,
        nullptr, nullptr, (float*)y);

    combine_kernel<<<(NTOK * (HIDDEN / 4)) / 256, 256>>>(scat, out);
}

// round 6
// speedup vs baseline: 2.6473x; 2.6473x over previous
#include <cuda_runtime.h>
#include <cuda_bf16.h>
#include <math.h>
#include <stdint.h>

// ---------------------------------------------------------------- constants
#define NTOK   8192
#define HIDDEN 2048
#define NEXP   8
#define TOPK   2
#define M_TOT  (NTOK * TOPK)      // 16384
#define CAP    (M_TOT / NEXP)     // 2048
#define KDIM   2048
#define NDIM   2048

constexpr int BM = 128, BN = 128, BK = 32;
constexpr int NS = 3;                          // pipeline ring slots
constexpr int NITER = KDIM / BK;               // 64
constexpr int NTILE_N = NDIM / BN;             // 16
constexpr int NTILE   = (M_TOT / BM) * NTILE_N; // 2048 tiles
constexpr int GRIDP   = 304;                   // persistent CTAs (2 x 152 SMs)
constexpr uint32_t TILE_BYTES  = 128 * 64;     // 8 KB: 128 rows x 32 bf16
constexpr uint32_t STAGE_BYTES = 4 * TILE_BYTES;   // Ah, Al, Bh, Bl = 32 KB
constexpr uint32_t SMEM_SZ     = NS * STAGE_BYTES; // 96 KB

// ---------------------------------------------------------------- scratch
__device__ __align__(1024) __nv_bfloat16 g_xs_hi[(size_t)M_TOT * KDIM];
__device__ __align__(1024) __nv_bfloat16 g_xs_lo[(size_t)M_TOT * KDIM];
__device__ __align__(1024) __nv_bfloat16 g_w1_hi[(size_t)NEXP * NDIM * KDIM];
__device__ __align__(1024) __nv_bfloat16 g_w1_lo[(size_t)NEXP * NDIM * KDIM];
__device__ __align__(1024) __nv_bfloat16 g_w2_hi[(size_t)NEXP * NDIM * KDIM];
__device__ __align__(1024) __nv_bfloat16 g_w2_lo[(size_t)NEXP * NDIM * KDIM];
__device__ __align__(1024) __nv_bfloat16 g_h_hi[(size_t)M_TOT * NDIM];
__device__ __align__(1024) __nv_bfloat16 g_h_lo[(size_t)M_TOT * NDIM];
__device__ __align__(1024) float         g_y[(size_t)M_TOT * HIDDEN];

// ---------------------------------------------------------------- helpers
__device__ __forceinline__ uint32_t smem_u32(const void* p) {
    uint32_t a;
    asm("{ .reg .u64 t; cvta.to.shared.u64 t, %1; cvt.u32.u64 %0, t; }"
        : "=r"(a) : "l"(p));
    return a;
}
__device__ __forceinline__ uint32_t sw128(uint32_t off) {
    return off ^ ((off >> 3) & 0x70);
}
__device__ __forceinline__ void cp16(uint32_t dst, const void* src) {
    asm volatile("cp.async.cg.shared.global [%0], [%1], 16;"
                 :: "r"(dst), "l"(src));
}
__device__ __forceinline__ void cp_commit() {
    asm volatile("cp.async.commit_group;");
}
template <int N>
__device__ __forceinline__ void cp_wait() {
    asm volatile("cp.async.wait_group %0;" :: "n"(N));
}
__device__ __forceinline__ void ldsm4(uint32_t* r, uint32_t addr) {
    asm volatile("ldmatrix.sync.aligned.m8n8.x4.shared.b16 {%0,%1,%2,%3}, [%4];"
                 : "=r"(r[0]), "=r"(r[1]), "=r"(r[2]), "=r"(r[3]) : "r"(addr));
}
__device__ __forceinline__ void mma_bf16(float* c, const uint32_t* a,
                                         const uint32_t* b) {
    asm volatile(
        "mma.sync.aligned.m16n8k16.row.col.f32.bf16.bf16.f32 "
        "{%0,%1,%2,%3},{%4,%5,%6,%7},{%8,%9},{%0,%1,%2,%3};"
        : "+f"(c[0]), "+f"(c[1]), "+f"(c[2]), "+f"(c[3])
        : "r"(a[0]), "r"(a[1]), "r"(a[2]), "r"(a[3]), "r"(b[0]), "r"(b[1]));
}

// ---------------------------------------------------------------- GEMM
// Persistent: each CTA loops over tiles (stride gridDim.x); the cp.async ring
// streams continuously across tile boundaries so the epilogue of tile t
// overlaps the prologue loads of tile t+1.
// C[r,n] = sum_k A[r,k]*W[e,n,k]  via bf16 3-term split, fp32 accumulate.
template <bool GELU>
__global__ void __launch_bounds__(256, 2)
gemm_pers(const __nv_bfloat16* __restrict__ Ah, const __nv_bfloat16* __restrict__ Al,
          const __nv_bfloat16* __restrict__ Wh, const __nv_bfloat16* __restrict__ Wl,
          __nv_bfloat16* __restrict__ out_hi, __nv_bfloat16* __restrict__ out_lo,
          float* __restrict__ out_f32) {
    extern __shared__ __align__(1024) char smem[];
    const uint32_t sb = smem_u32(smem);
    const int tid  = threadIdx.x;
    const int lane = tid & 31;
    const int w    = tid >> 5;
    const int wm   = w & 1;       // M half (64 rows)
    const int wn   = w >> 1;      // N quarter (32 cols)

    // ---- loader mapping: thread -> one of 4 term tiles, 8 x 16B per stage
    const int ltile = tid >> 6;          // 0..3 (Ah/Al/Wh/Wl)
    const int lch   = tid & 63;
    const int lr0   = lch >> 2;          // row 0..15
    const int lc    = lch & 3;           // 16B chunk
    const uint32_t soff0 = (uint32_t)ltile * TILE_BYTES + sw128(lr0 * 64 + lc * 16);

    auto gbase_of = [&](int tile) -> const __nv_bfloat16* {
        const int grow0 = (tile >> 4) * BM;
        const int gcol0 = (tile & 15) * BN;
        const int e     = tile >> 8;           // (tile>>4)/16
        if (ltile == 0) return Ah + (size_t)(grow0 + lr0) * KDIM + lc * 8;
        if (ltile == 1) return Al + (size_t)(grow0 + lr0) * KDIM + lc * 8;
        if (ltile == 2) return Wh + ((size_t)e * NDIM + gcol0 + lr0) * KDIM + lc * 8;
        return Wl + ((size_t)e * NDIM + gcol0 + lr0) * KDIM + lc * 8;
    };

    // ---- ldmatrix per-lane offsets
    const int ar  = lane & 15;
    const int akh = lane >> 4;
    const uint32_t aoff = sw128(ar * 64 + akh * 16);
    const int brn = lane & 7;
    const int bh  = (lane >> 3) & 1;
    const int bgs = lane >> 4;
    const int nrow0 = wn * 32 + bgs * 8 + brn;
    const uint32_t boff0 = sw128(nrow0 * 64 + bh * 16);
    const uint32_t boff1 = sw128((nrow0 + 16) * 64 + bh * 16);

    // ---- producer state (streams stages across tiles, 2 ahead of consumer)
    int ptile = blockIdx.x;
    int pit   = 0;
    const __nv_bfloat16* pbase = (ptile < NTILE) ? gbase_of(ptile) : Ah;

    auto produce = [&](int ring) {
        if (ptile < NTILE) {
            const uint32_t dst = sb + (uint32_t)ring * STAGE_BYTES + soff0;
            const __nv_bfloat16* src = pbase + pit * BK;
#pragma unroll
            for (int i = 0; i < 8; i++)
                cp16(dst + i * 1024, src + (size_t)i * 16 * KDIM);
            if (++pit == NITER) {
                pit = 0;
                ptile += GRIDP;
                if (ptile < NTILE) pbase = gbase_of(ptile);
            }
        }
        cp_commit();
    };

    produce(0);
    produce(1);
    int prc = 2;      // producer ring slot
    int crc = 0;      // consumer ring slot

    for (int tile = blockIdx.x; tile < NTILE; tile += GRIDP) {
        const int grow0 = (tile >> 4) * BM;
        const int gcol0 = (tile & 15) * BN;

        float acc[4][4][4];
#pragma unroll
        for (int i = 0; i < 4; i++)
#pragma unroll
            for (int j = 0; j < 4; j++)
#pragma unroll
                for (int k = 0; k < 4; k++) acc[i][j][k] = 0.f;

        for (int it = 0; it < NITER; it++) {
            cp_wait<1>();
            __syncthreads();
            produce(prc);
            prc = (prc == 2) ? 0 : prc + 1;
            const uint32_t base = sb + (uint32_t)crc * STAGE_BYTES;
            crc = (crc == 2) ? 0 : crc + 1;

#pragma unroll
            for (int kk = 0; kk < 2; kk++) {
                const uint32_t kx = (uint32_t)kk << 5;
                uint32_t bH[4][2], bL[4][2];
                {
                    uint32_t t0[4], t1[4];
                    ldsm4(t0, base + 2 * TILE_BYTES + (boff0 ^ kx));
                    bH[0][0] = t0[0]; bH[0][1] = t0[1];
                    bH[1][0] = t0[2]; bH[1][1] = t0[3];
                    ldsm4(t1, base + 2 * TILE_BYTES + (boff1 ^ kx));
                    bH[2][0] = t1[0]; bH[2][1] = t1[1];
                    bH[3][0] = t1[2]; bH[3][1] = t1[3];
                    ldsm4(t0, base + 3 * TILE_BYTES + (boff0 ^ kx));
                    bL[0][0] = t0[0]; bL[0][1] = t0[1];
                    bL[1][0] = t0[2]; bL[1][1] = t0[3];
                    ldsm4(t1, base + 3 * TILE_BYTES + (boff1 ^ kx));
                    bL[2][0] = t1[0]; bL[2][1] = t1[1];
                    bL[3][0] = t1[2]; bL[3][1] = t1[3];
                }
                const uint32_t aaddr = base + wm * 4096 + (aoff ^ kx);
#pragma unroll
                for (int mi = 0; mi < 4; mi++) {
                    uint32_t aH[4], aL[4];
                    ldsm4(aH, aaddr + mi * 1024);
                    ldsm4(aL, aaddr + TILE_BYTES + mi * 1024);
#pragma unroll
                    for (int g = 0; g < 4; g++) {
                        mma_bf16(acc[mi][g], aH, bH[g]);
                        mma_bf16(acc[mi][g], aH, bL[g]);
                        mma_bf16(acc[mi][g], aL, bH[g]);
                    }
                }
            }
        }

        // ---------------- epilogue (overlaps next tile's in-flight loads)
        const int r_in = lane >> 2;
        const int c_in = (lane & 3) * 2;
#pragma unroll
        for (int mi = 0; mi < 4; mi++) {
#pragma unroll
            for (int g = 0; g < 4; g++) {
                const int row0 = grow0 + wm * 64 + mi * 16 + r_in;
                const int col  = gcol0 + wn * 32 + g * 8 + c_in;
#pragma unroll
                for (int half = 0; half < 2; half++) {
                    const int row = row0 + half * 8;
                    float v0 = acc[mi][g][half * 2 + 0];
                    float v1 = acc[mi][g][half * 2 + 1];
                    const size_t off = (size_t)row * NDIM + col;
                    if (GELU) {
                        v0 = 0.5f * v0 * (1.0f + erff(v0 * 0.70710678118654752f));
                        v1 = 0.5f * v1 * (1.0f + erff(v1 * 0.70710678118654752f));
                        __nv_bfloat16 h0 = __float2bfloat16(v0);
                        __nv_bfloat16 h1 = __float2bfloat16(v1);
                        __nv_bfloat16 l0 = __float2bfloat16(v0 - __bfloat162float(h0));
                        __nv_bfloat16 l1 = __float2bfloat16(v1 - __bfloat162float(h1));
                        *(__nv_bfloat162*)(out_hi + off) = __nv_bfloat162(h0, h1);
                        *(__nv_bfloat162*)(out_lo + off) = __nv_bfloat162(l0, l1);
                    } else {
                        *(float2*)(out_f32 + off) = make_float2(v0, v1);
                    }
                }
            }
        }
    }
}

// ---------------------------------------------------------------- conversions
__global__ void split_kernel(const float* __restrict__ in,
                             __nv_bfloat16* __restrict__ hi,
                             __nv_bfloat16* __restrict__ lo) {
    const size_t i = (size_t)blockIdx.x * blockDim.x + threadIdx.x; // over n/4
    float4 v = ((const float4*)in)[i];
    __nv_bfloat16 h0 = __float2bfloat16(v.x), h1 = __float2bfloat16(v.y);
    __nv_bfloat16 h2 = __float2bfloat16(v.z), h3 = __float2bfloat16(v.w);
    __nv_bfloat16 l0 = __float2bfloat16(v.x - __bfloat162float(h0));
    __nv_bfloat16 l1 = __float2bfloat16(v.y - __bfloat162float(h1));
    __nv_bfloat16 l2 = __float2bfloat16(v.z - __bfloat162float(h2));
    __nv_bfloat16 l3 = __float2bfloat16(v.w - __bfloat162float(h3));
    ((__nv_bfloat162*)hi)[2 * i]     = __nv_bfloat162(h0, h1);
    ((__nv_bfloat162*)hi)[2 * i + 1] = __nv_bfloat162(h2, h3);
    ((__nv_bfloat162*)lo)[2 * i]     = __nv_bfloat162(l0, l1);
    ((__nv_bfloat162*)lo)[2 * i + 1] = __nv_bfloat162(l2, l3);
}

__global__ void scatter_split_kernel(const float* __restrict__ x,
                                     const int* __restrict__ scat,
                                     __nv_bfloat16* __restrict__ hi,
                                     __nv_bfloat16* __restrict__ lo) {
    const int p = blockIdx.x;                 // [0, M_TOT)
    const int d = scat[p];
    const float4* src = (const float4*)(x + (size_t)(p >> 1) * HIDDEN);
    __nv_bfloat162* dh = (__nv_bfloat162*)(hi + (size_t)d * HIDDEN);
    __nv_bfloat162* dl = (__nv_bfloat162*)(lo + (size_t)d * HIDDEN);
    for (int c = threadIdx.x; c < HIDDEN / 4; c += blockDim.x) {
        float4 v = src[c];
        __nv_bfloat16 h0 = __float2bfloat16(v.x), h1 = __float2bfloat16(v.y);
        __nv_bfloat16 h2 = __float2bfloat16(v.z), h3 = __float2bfloat16(v.w);
        dh[2 * c]     = __nv_bfloat162(h0, h1);
        dh[2 * c + 1] = __nv_bfloat162(h2, h3);
        dl[2 * c]     = __nv_bfloat162(__float2bfloat16(v.x - __bfloat162float(h0)),
                                       __float2bfloat16(v.y - __bfloat162float(h1)));
        dl[2 * c + 1] = __nv_bfloat162(__float2bfloat16(v.z - __bfloat162float(h2)),
                                       __float2bfloat16(v.w - __bfloat162float(h3)));
    }
}

__global__ void combine_kernel(const int* __restrict__ scat, float* __restrict__ out) {
    const int idx = blockIdx.x * blockDim.x + threadIdx.x;   // NTOK * HIDDEN/4
    const int t  = idx / (HIDDEN / 4);
    const int c4 = (idx % (HIDDEN / 4)) * 4;
    const int s0 = scat[t * TOPK + 0];
    const int s1 = scat[t * TOPK + 1];
    float4 v0 = *(const float4*)(g_y + (size_t)s0 * HIDDEN + c4);
    float4 v1 = *(const float4*)(g_y + (size_t)s1 * HIDDEN + c4);
    *(float4*)(out + (size_t)t * HIDDEN + c4) =
        make_float4(v0.x + v1.x, v0.y + v1.y, v0.z + v1.z, v0.w + v1.w);
}

// ---------------------------------------------------------------- host
extern "C" void kernel_launch(void* const* d_in, const int* in_sizes, int n_in,
                              void* d_out, int out_size) {
    const float* x    = (const float*)d_in[0];
    const float* w1   = (const float*)d_in[1];
    const float* w2   = (const float*)d_in[2];
    const int*   scat = (const int*)d_in[3];
    float* out = (float*)d_out;

    void *xs_hi, *xs_lo, *w1h, *w1l, *w2h, *w2l, *hh, *hl;
    cudaGetSymbolAddress(&xs_hi, g_xs_hi);
    cudaGetSymbolAddress(&xs_lo, g_xs_lo);
    cudaGetSymbolAddress(&w1h, g_w1_hi);
    cudaGetSymbolAddress(&w1l, g_w1_lo);
    cudaGetSymbolAddress(&w2h, g_w2_hi);
    cudaGetSymbolAddress(&w2l, g_w2_lo);
    cudaGetSymbolAddress(&hh, g_h_hi);
    cudaGetSymbolAddress(&hl, g_h_lo);
    float* ybuf = nullptr;
    cudaGetSymbolAddress((void**)&ybuf, g_y);

    cudaFuncSetAttribute(gemm_pers<true>,  cudaFuncAttributeMaxDynamicSharedMemorySize,
                         (int)SMEM_SZ);
    cudaFuncSetAttribute(gemm_pers<false>, cudaFuncAttributeMaxDynamicSharedMemorySize,
                         (int)SMEM_SZ);

    // conversions
    split_kernel<<<(NEXP * NDIM * KDIM) / (256 * 4), 256>>>(
        w1, (__nv_bfloat16*)w1h, (__nv_bfloat16*)w1l);
    split_kernel<<<(NEXP * NDIM * KDIM) / (256 * 4), 256>>>(
        w2, (__nv_bfloat16*)w2h, (__nv_bfloat16*)w2l);
    scatter_split_kernel<<<M_TOT, 256>>>(x, scat, (__nv_bfloat16*)xs_hi,
                                         (__nv_bfloat16*)xs_lo);

    // fc1: x_scat @ w1^T -> gelu -> h (bf16 hi/lo)
    gemm_pers<true><<<GRIDP, 256, SMEM_SZ>>>(
        (const __nv_bfloat16*)xs_hi, (const __nv_bfloat16*)xs_lo,
        (const __nv_bfloat16*)w1h, (const __nv_bfloat16*)w1l,
        (__nv_bfloat16*)hh, (__nv_bfloat16*)hl, nullptr);

    // fc2: h @ w2^T -> y (f32)
    gemm_pers<false><<<GRIDP, 256, SMEM_SZ>>>(
        (const __nv_bfloat16*)hh, (const __nv_bfloat16*)hl,
        (const __nv_bfloat16*)w2h, (const __nv_bfloat16*)w2l,
        nullptr, nullptr, ybuf);

    combine_kernel<<<(NTOK * (HIDDEN / 4)) / 256, 256>>>(scat, out);
}

// round 7
// speedup vs baseline: 4.1611x; 1.5719x over previous
#include <cuda_runtime.h>
#include <cuda_fp16.h>
#include <math.h>
#include <stdint.h>

// ---------------------------------------------------------------- constants
#define NTOK   8192
#define HIDDEN 2048
#define NEXP   8
#define TOPK   2
#define M_TOT  (NTOK * TOPK)      // 16384
#define CAP    (M_TOT / NEXP)     // 2048
#define KDIM   2048
#define NDIM   2048

constexpr int BM = 128, BN = 128, BK = 32;
constexpr int NS = 4;                          // pipeline ring slots
constexpr int NITER = KDIM / BK;               // 64
constexpr uint32_t TILE_BYTES  = 128 * 64;     // 8 KB: 128 rows x 32 fp16
constexpr uint32_t OFF_A  = 0;
constexpr uint32_t OFF_BH = TILE_BYTES;
constexpr uint32_t OFF_BL = 2 * TILE_BYTES;
constexpr uint32_t STAGE_BYTES = 3 * TILE_BYTES;   // 24 KB
constexpr uint32_t SMEM_SZ     = NS * STAGE_BYTES; // 96 KB

constexpr float WSCALE    = 32.0f;             // weights pre-scaled into fp16 range
constexpr float WSCALEINV = 1.0f / 32.0f;

// ---------------------------------------------------------------- scratch
__device__ __align__(1024) __half g_xq[(size_t)M_TOT * KDIM];           // fp16(x), scattered
__device__ __align__(1024) __half g_w1h[(size_t)NEXP * NDIM * KDIM];
__device__ __align__(1024) __half g_w1l[(size_t)NEXP * NDIM * KDIM];
__device__ __align__(1024) __half g_w2h[(size_t)NEXP * NDIM * KDIM];
__device__ __align__(1024) __half g_w2l[(size_t)NEXP * NDIM * KDIM];
__device__ __align__(1024) __half g_h[(size_t)M_TOT * NDIM];            // fp16(gelu)
__device__ __align__(1024) float  g_y[(size_t)M_TOT * HIDDEN];

// ---------------------------------------------------------------- helpers
__device__ __forceinline__ uint32_t smem_u32(const void* p) {
    uint32_t a;
    asm("{ .reg .u64 t; cvta.to.shared.u64 t, %1; cvt.u32.u64 %0, t; }"
        : "=r"(a) : "l"(p));
    return a;
}
__device__ __forceinline__ uint32_t sw128(uint32_t off) {
    return off ^ ((off >> 3) & 0x70);
}
__device__ __forceinline__ void cp16(uint32_t dst, const void* src) {
    asm volatile("cp.async.cg.shared.global [%0], [%1], 16;"
                 :: "r"(dst), "l"(src));
}
__device__ __forceinline__ void cp_commit() {
    asm volatile("cp.async.commit_group;");
}
template <int N>
__device__ __forceinline__ void cp_wait() {
    asm volatile("cp.async.wait_group %0;" :: "n"(N));
}
__device__ __forceinline__ void ldsm4(uint32_t* r, uint32_t addr) {
    asm volatile("ldmatrix.sync.aligned.m8n8.x4.shared.b16 {%0,%1,%2,%3}, [%4];"
                 : "=r"(r[0]), "=r"(r[1]), "=r"(r[2]), "=r"(r[3]) : "r"(addr));
}
__device__ __forceinline__ void mma_f16(float* c, const uint32_t* a,
                                        const uint32_t* b) {
    asm volatile(
        "mma.sync.aligned.m16n8k16.row.col.f32.f16.f16.f32 "
        "{%0,%1,%2,%3},{%4,%5,%6,%7},{%8,%9},{%0,%1,%2,%3};"
        : "+f"(c[0]), "+f"(c[1]), "+f"(c[2]), "+f"(c[3])
        : "r"(a[0]), "r"(a[1]), "r"(a[2]), "r"(a[3]), "r"(b[0]), "r"(b[1]));
}

// ---------------------------------------------------------------- GEMM
// C[r,n] = (1/32) * sum_k A[r,k] * (Wh[e,n,k] + Wl[e,n,k])
// A: single fp16.  W: 2-term fp16 split of 32*w.  fp32 accumulate.
template <bool GELU>
__global__ void __launch_bounds__(256, 2)
gemm_f16(const __half* __restrict__ A,
         const __half* __restrict__ Wh, const __half* __restrict__ Wl,
         __half* __restrict__ out_h, float* __restrict__ out_f32) {
    extern __shared__ __align__(1024) char smem[];
    const uint32_t sb = smem_u32(smem);
    const int tid  = threadIdx.x;
    const int lane = tid & 31;
    const int w    = tid >> 5;
    const int wm   = w & 1;       // M half (64 rows)
    const int wn   = w >> 1;      // N quarter (32 cols)
    const int grow0 = blockIdx.y * BM;
    const int gcol0 = blockIdx.x * BN;
    const int e     = grow0 / CAP;

    // ---- loader: 6 x 16B per thread per stage (A, Bh, Bl; rows lr & lr+64)
    const int lr = tid >> 2;             // 0..63
    const int lc = tid & 3;              // 16B chunk
    const uint32_t s_lo = sw128((uint32_t)lr * 64 + lc * 16);
    const uint32_t s_hi = sw128((uint32_t)(64 + lr) * 64 + lc * 16);
    const __half* a0 = A  + (size_t)(grow0 + lr) * KDIM + lc * 8;
    const __half* a1 = A  + (size_t)(grow0 + 64 + lr) * KDIM + lc * 8;
    const __half* h0 = Wh + ((size_t)e * NDIM + gcol0 + lr) * KDIM + lc * 8;
    const __half* h1 = h0 + (size_t)64 * KDIM;
    const __half* l0 = Wl + ((size_t)e * NDIM + gcol0 + lr) * KDIM + lc * 8;
    const __half* l1 = l0 + (size_t)64 * KDIM;

    auto load_stage = [&](int it) {
        if (it < NITER) {
            const uint32_t base = sb + (uint32_t)(it & 3) * STAGE_BYTES;
            const int ko = it * BK;
            cp16(base + OFF_A  + s_lo, a0 + ko);
            cp16(base + OFF_A  + s_hi, a1 + ko);
            cp16(base + OFF_BH + s_lo, h0 + ko);
            cp16(base + OFF_BH + s_hi, h1 + ko);
            cp16(base + OFF_BL + s_lo, l0 + ko);
            cp16(base + OFF_BL + s_hi, l1 + ko);
        }
        cp_commit();
    };

    // ---- ldmatrix per-lane offsets
    const int ar  = lane & 15;
    const int akh = lane >> 4;
    const uint32_t aoff = sw128((uint32_t)ar * 64 + akh * 16);
    const int brn = lane & 7;
    const int bh  = (lane >> 3) & 1;
    const int bgs = lane >> 4;
    const int nrow0 = wn * 32 + bgs * 8 + brn;
    const uint32_t boff0 = sw128((uint32_t)nrow0 * 64 + bh * 16);
    const uint32_t boff1 = sw128((uint32_t)(nrow0 + 16) * 64 + bh * 16);

    float acc[4][4][4];
#pragma unroll
    for (int i = 0; i < 4; i++)
#pragma unroll
        for (int j = 0; j < 4; j++)
#pragma unroll
            for (int k = 0; k < 4; k++) acc[i][j][k] = 0.f;

    load_stage(0);
    load_stage(1);
    load_stage(2);

    for (int it = 0; it < NITER; it++) {
        cp_wait<2>();
        __syncthreads();
        load_stage(it + 3);

        const uint32_t base = sb + (uint32_t)(it & 3) * STAGE_BYTES;
#pragma unroll
        for (int kk = 0; kk < 2; kk++) {
            const uint32_t kx = (uint32_t)kk << 5;
            uint32_t bH[4][2], bL[4][2];
            {
                uint32_t t0[4], t1[4];
                ldsm4(t0, base + OFF_BH + (boff0 ^ kx));
                bH[0][0] = t0[0]; bH[0][1] = t0[1];
                bH[1][0] = t0[2]; bH[1][1] = t0[3];
                ldsm4(t1, base + OFF_BH + (boff1 ^ kx));
                bH[2][0] = t1[0]; bH[2][1] = t1[1];
                bH[3][0] = t1[2]; bH[3][1] = t1[3];
                ldsm4(t0, base + OFF_BL + (boff0 ^ kx));
                bL[0][0] = t0[0]; bL[0][1] = t0[1];
                bL[1][0] = t0[2]; bL[1][1] = t0[3];
                ldsm4(t1, base + OFF_BL + (boff1 ^ kx));
                bL[2][0] = t1[0]; bL[2][1] = t1[1];
                bL[3][0] = t1[2]; bL[3][1] = t1[3];
            }
            const uint32_t aaddr = base + OFF_A + wm * 4096 + (aoff ^ kx);
#pragma unroll
            for (int mi = 0; mi < 4; mi++) {
                uint32_t aF[4];
                ldsm4(aF, aaddr + mi * 1024);
#pragma unroll
                for (int g = 0; g < 4; g++) {
                    mma_f16(acc[mi][g], aF, bH[g]);
                    mma_f16(acc[mi][g], aF, bL[g]);
                }
            }
        }
    }

    // ---------------- epilogue
    const int r_in = lane >> 2;
    const int c_in = (lane & 3) * 2;
#pragma unroll
    for (int mi = 0; mi < 4; mi++) {
#pragma unroll
        for (int g = 0; g < 4; g++) {
            const int row0 = grow0 + wm * 64 + mi * 16 + r_in;
            const int col  = gcol0 + wn * 32 + g * 8 + c_in;
#pragma unroll
            for (int half = 0; half < 2; half++) {
                const int row = row0 + half * 8;
                float v0 = acc[mi][g][half * 2 + 0] * WSCALEINV;
                float v1 = acc[mi][g][half * 2 + 1] * WSCALEINV;
                const size_t off = (size_t)row * NDIM + col;
                if (GELU) {
                    v0 = 0.5f * v0 * (1.0f + erff(v0 * 0.70710678118654752f));
                    v1 = 0.5f * v1 * (1.0f + erff(v1 * 0.70710678118654752f));
                    *(__half2*)(out_h + off) =
                        __halves2half2(__float2half(v0), __float2half(v1));
                } else {
                    *(float2*)(out_f32 + off) = make_float2(v0, v1);
                }
            }
        }
    }
}

// ---------------------------------------------------------------- conversions
// Weights: t = 32*w; wh = fp16(t); wl = fp16(t - wh).
__global__ void split_w_kernel(const float* __restrict__ in,
                               __half* __restrict__ hi, __half* __restrict__ lo) {
    const size_t i = (size_t)blockIdx.x * blockDim.x + threadIdx.x; // over n/4
    float4 v = ((const float4*)in)[i];
    float t0 = v.x * WSCALE, t1 = v.y * WSCALE, t2 = v.z * WSCALE, t3 = v.w * WSCALE;
    __half h0 = __float2half(t0), h1 = __float2half(t1);
    __half h2 = __float2half(t2), h3 = __float2half(t3);
    ((__half2*)hi)[2 * i]     = __halves2half2(h0, h1);
    ((__half2*)hi)[2 * i + 1] = __halves2half2(h2, h3);
    ((__half2*)lo)[2 * i]     = __halves2half2(__float2half(t0 - __half2float(h0)),
                                               __float2half(t1 - __half2float(h1)));
    ((__half2*)lo)[2 * i + 1] = __halves2half2(__float2half(t2 - __half2float(h2)),
                                               __float2half(t3 - __half2float(h3)));
}

// x -> fp16, scattered to expert-sorted rows.
__global__ void scatter_q_kernel(const float* __restrict__ x,
                                 const int* __restrict__ scat,
                                 __half* __restrict__ q) {
    const int p = blockIdx.x;                 // [0, M_TOT)
    const int d = scat[p];
    const float4* src = (const float4*)(x + (size_t)(p >> 1) * HIDDEN);
    __half2* dq = (__half2*)(q + (size_t)d * HIDDEN);
    for (int c = threadIdx.x; c < HIDDEN / 4; c += blockDim.x) {
        float4 v = src[c];
        dq[2 * c]     = __halves2half2(__float2half(v.x), __float2half(v.y));
        dq[2 * c + 1] = __halves2half2(__float2half(v.z), __float2half(v.w));
    }
}

__global__ void combine_kernel(const int* __restrict__ scat, float* __restrict__ out) {
    const int idx = blockIdx.x * blockDim.x + threadIdx.x;   // NTOK * HIDDEN/4
    const int t  = idx / (HIDDEN / 4);
    const int c4 = (idx % (HIDDEN / 4)) * 4;
    const int s0 = scat[t * TOPK + 0];
    const int s1 = scat[t * TOPK + 1];
    float4 v0 = *(const float4*)(g_y + (size_t)s0 * HIDDEN + c4);
    float4 v1 = *(const float4*)(g_y + (size_t)s1 * HIDDEN + c4);
    *(float4*)(out + (size_t)t * HIDDEN + c4) =
        make_float4(v0.x + v1.x, v0.y + v1.y, v0.z + v1.z, v0.w + v1.w);
}

// ---------------------------------------------------------------- host
extern "C" void kernel_launch(void* const* d_in, const int* in_sizes, int n_in,
                              void* d_out, int out_size) {
    const float* x    = (const float*)d_in[0];
    const float* w1   = (const float*)d_in[1];
    const float* w2   = (const float*)d_in[2];
    const int*   scat = (const int*)d_in[3];
    float* out = (float*)d_out;

    void *xq, *w1h, *w1l, *w2h, *w2l, *hb, *yb;
    cudaGetSymbolAddress(&xq, g_xq);
    cudaGetSymbolAddress(&w1h, g_w1h);
    cudaGetSymbolAddress(&w1l, g_w1l);
    cudaGetSymbolAddress(&w2h, g_w2h);
    cudaGetSymbolAddress(&w2l, g_w2l);
    cudaGetSymbolAddress(&hb, g_h);
    cudaGetSymbolAddress(&yb, g_y);

    cudaFuncSetAttribute(gemm_f16<true>,  cudaFuncAttributeMaxDynamicSharedMemorySize,
                         (int)SMEM_SZ);
    cudaFuncSetAttribute(gemm_f16<false>, cudaFuncAttributeMaxDynamicSharedMemorySize,
                         (int)SMEM_SZ);

    // conversions
    split_w_kernel<<<(NEXP * NDIM * KDIM) / (256 * 4), 256>>>(
        w1, (__half*)w1h, (__half*)w1l);
    split_w_kernel<<<(NEXP * NDIM * KDIM) / (256 * 4), 256>>>(
        w2, (__half*)w2h, (__half*)w2l);
    scatter_q_kernel<<<M_TOT, 256>>>(x, scat, (__half*)xq);

    // fc1: x @ w1^T -> gelu -> h (fp16)
    gemm_f16<true><<<dim3(NDIM / BN, M_TOT / BM), 256, SMEM_SZ>>>(
        (const __half*)xq, (const __half*)w1h, (const __half*)w1l,
        (__half*)hb, nullptr);

    // fc2: h @ w2^T -> y (f32)
    gemm_f16<false><<<dim3(HIDDEN / BN, M_TOT / BM), 256, SMEM_SZ>>>(
        (const __half*)hb, (const __half*)w2h, (const __half*)w2l,
        nullptr, (float*)yb);

    combine_kernel<<<(NTOK * (HIDDEN / 4)) / 256, 256>>>(scat, out);
}

// round 8
// speedup vs baseline: 4.2732x; 1.0269x over previous
#include <cuda_runtime.h>
#include <cuda_fp16.h>
#include <math.h>
#include <stdint.h>

// ---------------------------------------------------------------- constants
#define NTOK   8192
#define HIDDEN 2048
#define NEXP   8
#define TOPK   2
#define M_TOT  (NTOK * TOPK)      // 16384
#define CAP    (M_TOT / NEXP)     // 2048
#define KDIM   2048
#define NDIM   2048

constexpr int BM = 128, BN = 128, BK = 32;
constexpr int NS = 4;                          // pipeline ring slots
constexpr int NITER = KDIM / BK;               // 64
constexpr uint32_t TILE_BYTES  = 128 * 64;     // 8 KB: 128 rows x 32 fp16
constexpr uint32_t OFF_A = 0;
constexpr uint32_t OFF_B = TILE_BYTES;
constexpr uint32_t STAGE_BYTES = 2 * TILE_BYTES;   // 16 KB
constexpr uint32_t SMEM_SZ     = NS * STAGE_BYTES; // 64 KB

constexpr float WSCALE    = 32.0f;             // weights pre-scaled into fp16 range
constexpr float WSCALEINV = 1.0f / 32.0f;

// ---------------------------------------------------------------- scratch
__device__ __align__(1024) __half g_xq[(size_t)M_TOT * KDIM];       // fp16(x), scattered
__device__ __align__(1024) __half g_w1q[(size_t)NEXP * NDIM * KDIM];
__device__ __align__(1024) __half g_w2q[(size_t)NEXP * NDIM * KDIM];
__device__ __align__(1024) __half g_h[(size_t)M_TOT * NDIM];        // fp16(gelu)
__device__ __align__(1024) float  g_y[(size_t)M_TOT * HIDDEN];

// ---------------------------------------------------------------- helpers
__device__ __forceinline__ uint32_t smem_u32(const void* p) {
    uint32_t a;
    asm("{ .reg .u64 t; cvta.to.shared.u64 t, %1; cvt.u32.u64 %0, t; }"
        : "=r"(a) : "l"(p));
    return a;
}
__device__ __forceinline__ uint32_t sw128(uint32_t off) {
    return off ^ ((off >> 3) & 0x70);
}
__device__ __forceinline__ void cp16(uint32_t dst, const void* src) {
    asm volatile("cp.async.cg.shared.global [%0], [%1], 16;"
                 :: "r"(dst), "l"(src));
}
__device__ __forceinline__ void cp_commit() {
    asm volatile("cp.async.commit_group;");
}
template <int N>
__device__ __forceinline__ void cp_wait() {
    asm volatile("cp.async.wait_group %0;" :: "n"(N));
}
__device__ __forceinline__ void ldsm4(uint32_t* r, uint32_t addr) {
    asm volatile("ldmatrix.sync.aligned.m8n8.x4.shared.b16 {%0,%1,%2,%3}, [%4];"
                 : "=r"(r[0]), "=r"(r[1]), "=r"(r[2]), "=r"(r[3]) : "r"(addr));
}
__device__ __forceinline__ void mma_f16(float* c, const uint32_t* a,
                                        const uint32_t* b) {
    asm volatile(
        "mma.sync.aligned.m16n8k16.row.col.f32.f16.f16.f32 "
        "{%0,%1,%2,%3},{%4,%5,%6,%7},{%8,%9},{%0,%1,%2,%3};"
        : "+f"(c[0]), "+f"(c[1]), "+f"(c[2]), "+f"(c[3])
        : "r"(a[0]), "r"(a[1]), "r"(a[2]), "r"(a[3]), "r"(b[0]), "r"(b[1]));
}

// ---------------------------------------------------------------- GEMM
// C[r,n] = (1/32) * sum_k A[r,k] * Wq[e,n,k]   (A fp16, Wq = fp16(32*w))
template <bool GELU>
__global__ void __launch_bounds__(256, 2)
gemm_f16(const __half* __restrict__ A, const __half* __restrict__ Wq,
         __half* __restrict__ out_h, float* __restrict__ out_f32) {
    extern __shared__ __align__(1024) char smem[];
    const uint32_t sb = smem_u32(smem);
    const int tid  = threadIdx.x;
    const int lane = tid & 31;
    const int w    = tid >> 5;
    const int wm   = w & 1;       // M half (64 rows)
    const int wn   = w >> 1;      // N quarter (32 cols)
    const int grow0 = blockIdx.y * BM;
    const int gcol0 = blockIdx.x * BN;
    const int e     = grow0 / CAP;

    // ---- loader: 4 x 16B per thread per stage (A or B tile, one full row)
    const int ltile = tid >> 7;          // 0 = A, 1 = B
    const int lr    = tid & 127;         // row 0..127
    const uint32_t s_r0 = sw128((uint32_t)lr * 64);
    const uint32_t s_r1 = sw128((uint32_t)lr * 64 + 16);
    const uint32_t s_r2 = sw128((uint32_t)lr * 64 + 32);
    const uint32_t s_r3 = sw128((uint32_t)lr * 64 + 48);
    const uint32_t toff = (uint32_t)ltile * TILE_BYTES;
    const __half* gsrc = (ltile == 0)
        ? A  + (size_t)(grow0 + lr) * KDIM
        : Wq + ((size_t)e * NDIM + gcol0 + lr) * KDIM;

    auto load_stage = [&](int it) {
        if (it < NITER) {
            const uint32_t base = sb + (uint32_t)(it & 3) * STAGE_BYTES + toff;
            const __half* src = gsrc + it * BK;
            cp16(base + s_r0, src);
            cp16(base + s_r1, src + 8);
            cp16(base + s_r2, src + 16);
            cp16(base + s_r3, src + 24);
        }
        cp_commit();
    };

    // ---- ldmatrix per-lane offsets
    const int ar  = lane & 15;
    const int akh = lane >> 4;
    const uint32_t aoff = sw128((uint32_t)ar * 64 + akh * 16);
    const int brn = lane & 7;
    const int bh  = (lane >> 3) & 1;
    const int bgs = lane >> 4;
    const int nrow0 = wn * 32 + bgs * 8 + brn;
    const uint32_t boff0 = sw128((uint32_t)nrow0 * 64 + bh * 16);
    const uint32_t boff1 = sw128((uint32_t)(nrow0 + 16) * 64 + bh * 16);

    float acc[4][4][4];
#pragma unroll
    for (int i = 0; i < 4; i++)
#pragma unroll
        for (int j = 0; j < 4; j++)
#pragma unroll
            for (int k = 0; k < 4; k++) acc[i][j][k] = 0.f;

    load_stage(0);
    load_stage(1);
    load_stage(2);

    for (int it = 0; it < NITER; it++) {
        cp_wait<2>();
        __syncthreads();
        load_stage(it + 3);

        const uint32_t base = sb + (uint32_t)(it & 3) * STAGE_BYTES;
#pragma unroll
        for (int kk = 0; kk < 2; kk++) {
            const uint32_t kx = (uint32_t)kk << 5;
            uint32_t bF[4][2];
            {
                uint32_t t0[4], t1[4];
                ldsm4(t0, base + OFF_B + (boff0 ^ kx));
                bF[0][0] = t0[0]; bF[0][1] = t0[1];
                bF[1][0] = t0[2]; bF[1][1] = t0[3];
                ldsm4(t1, base + OFF_B + (boff1 ^ kx));
                bF[2][0] = t1[0]; bF[2][1] = t1[1];
                bF[3][0] = t1[2]; bF[3][1] = t1[3];
            }
            const uint32_t aaddr = base + OFF_A + wm * 4096 + (aoff ^ kx);
#pragma unroll
            for (int mi = 0; mi < 4; mi++) {
                uint32_t aF[4];
                ldsm4(aF, aaddr + mi * 1024);
#pragma unroll
                for (int g = 0; g < 4; g++)
                    mma_f16(acc[mi][g], aF, bF[g]);
            }
        }
    }

    // ---------------- epilogue
    const int r_in = lane >> 2;
    const int c_in = (lane & 3) * 2;
#pragma unroll
    for (int mi = 0; mi < 4; mi++) {
#pragma unroll
        for (int g = 0; g < 4; g++) {
            const int row0 = grow0 + wm * 64 + mi * 16 + r_in;
            const int col  = gcol0 + wn * 32 + g * 8 + c_in;
#pragma unroll
            for (int half = 0; half < 2; half++) {
                const int row = row0 + half * 8;
                float v0 = acc[mi][g][half * 2 + 0] * WSCALEINV;
                float v1 = acc[mi][g][half * 2 + 1] * WSCALEINV;
                const size_t off = (size_t)row * NDIM + col;
                if (GELU) {
                    v0 = 0.5f * v0 * (1.0f + erff(v0 * 0.70710678118654752f));
                    v1 = 0.5f * v1 * (1.0f + erff(v1 * 0.70710678118654752f));
                    *(__half2*)(out_h + off) =
                        __halves2half2(__float2half(v0), __float2half(v1));
                } else {
                    *(float2*)(out_f32 + off) = make_float2(v0, v1);
                }
            }
        }
    }
}

// ---------------------------------------------------------------- conversions
// Weights: wq = fp16(32*w).
__global__ void quant_w_kernel(const float* __restrict__ in,
                               __half* __restrict__ q) {
    const size_t i = (size_t)blockIdx.x * blockDim.x + threadIdx.x; // over n/4
    float4 v = ((const float4*)in)[i];
    ((__half2*)q)[2 * i]     = __halves2half2(__float2half(v.x * WSCALE),
                                              __float2half(v.y * WSCALE));
    ((__half2*)q)[2 * i + 1] = __halves2half2(__float2half(v.z * WSCALE),
                                              __float2half(v.w * WSCALE));
}

// x -> fp16, scattered to expert-sorted rows.
__global__ void scatter_q_kernel(const float* __restrict__ x,
                                 const int* __restrict__ scat,
                                 __half* __restrict__ q) {
    const int p = blockIdx.x;                 // [0, M_TOT)
    const int d = scat[p];
    const float4* src = (const float4*)(x + (size_t)(p >> 1) * HIDDEN);
    __half2* dq = (__half2*)(q + (size_t)d * HIDDEN);
    for (int c = threadIdx.x; c < HIDDEN / 4; c += blockDim.x) {
        float4 v = src[c];
        dq[2 * c]     = __halves2half2(__float2half(v.x), __float2half(v.y));
        dq[2 * c + 1] = __halves2half2(__float2half(v.z), __float2half(v.w));
    }
}

__global__ void combine_kernel(const int* __restrict__ scat, float* __restrict__ out) {
    const int idx = blockIdx.x * blockDim.x + threadIdx.x;   // NTOK * HIDDEN/4
    const int t  = idx / (HIDDEN / 4);
    const int c4 = (idx % (HIDDEN / 4)) * 4;
    const int s0 = scat[t * TOPK + 0];
    const int s1 = scat[t * TOPK + 1];
    float4 v0 = *(const float4*)(g_y + (size_t)s0 * HIDDEN + c4);
    float4 v1 = *(const float4*)(g_y + (size_t)s1 * HIDDEN + c4);
    *(float4*)(out + (size_t)t * HIDDEN + c4) =
        make_float4(v0.x + v1.x, v0.y + v1.y, v0.z + v1.z, v0.w + v1.w);
}

// ---------------------------------------------------------------- host
extern "C" void kernel_launch(void* const* d_in, const int* in_sizes, int n_in,
                              void* d_out, int out_size) {
    const float* x    = (const float*)d_in[0];
    const float* w1   = (const float*)d_in[1];
    const float* w2   = (const float*)d_in[2];
    const int*   scat = (const int*)d_in[3];
    float* out = (float*)d_out;

    void *xq, *w1q, *w2q, *hb, *yb;
    cudaGetSymbolAddress(&xq, g_xq);
    cudaGetSymbolAddress(&w1q, g_w1q);
    cudaGetSymbolAddress(&w2q, g_w2q);
    cudaGetSymbolAddress(&hb, g_h);
    cudaGetSymbolAddress(&yb, g_y);

    cudaFuncSetAttribute(gemm_f16<true>,  cudaFuncAttributeMaxDynamicSharedMemorySize,
                         (int)SMEM_SZ);
    cudaFuncSetAttribute(gemm_f16<false>, cudaFuncAttributeMaxDynamicSharedMemorySize,
                         (int)SMEM_SZ);

    // conversions
    quant_w_kernel<<<(NEXP * NDIM * KDIM) / (256 * 4), 256>>>(w1, (__half*)w1q);
    quant_w_kernel<<<(NEXP * NDIM * KDIM) / (256 * 4), 256>>>(w2, (__half*)w2q);
    scatter_q_kernel<<<M_TOT, 256>>>(x, scat, (__half*)xq);

    // fc1: x @ w1^T -> gelu -> h (fp16)
    gemm_f16<true><<<dim3(NDIM / BN, M_TOT / BM), 256, SMEM_SZ>>>(
        (const __half*)xq, (const __half*)w1q, (__half*)hb, nullptr);

    // fc2: h @ w2^T -> y (f32)
    gemm_f16<false><<<dim3(HIDDEN / BN, M_TOT / BM), 256, SMEM_SZ>>>(
        (const __half*)hb, (const __half*)w2q, nullptr, (float*)yb);

    combine_kernel<<<(NTOK * (HIDDEN / 4)) / 256, 256>>>(scat, out);
}

// round 9
// speedup vs baseline: 6.7246x; 1.5737x over previous
#include <cuda_runtime.h>
#include <cuda_fp16.h>
#include <math.h>
#include <stdint.h>

// ---------------------------------------------------------------- constants
#define NTOK   8192
#define HIDDEN 2048
#define NEXP   8
#define TOPK   2
#define M_TOT  (NTOK * TOPK)      // 16384
#define CAP    (M_TOT / NEXP)     // 2048
#define KDIM   2048
#define NDIM   2048

constexpr int BM = 128, BN = 128, BK = 64;
constexpr int NS = 3;                          // pipeline ring slots
constexpr int NITER = KDIM / BK;               // 32
constexpr uint32_t TILE_BYTES  = 128 * 128;    // 16 KB: 128 rows x 64 fp16 (128B rows)
constexpr uint32_t OFF_A = 0;
constexpr uint32_t OFF_B = TILE_BYTES;
constexpr uint32_t STAGE_BYTES = 2 * TILE_BYTES;   // 32 KB
constexpr uint32_t SMEM_SZ     = NS * STAGE_BYTES; // 96 KB

constexpr float WSCALE    = 32.0f;             // weights pre-scaled into fp16 range
constexpr float WSCALEINV = 1.0f / 32.0f;

// ---------------------------------------------------------------- scratch
__device__ __align__(1024) __half g_xq[(size_t)M_TOT * KDIM];       // fp16(x), scattered
__device__ __align__(1024) __half g_w1q[(size_t)NEXP * NDIM * KDIM];
__device__ __align__(1024) __half g_w2q[(size_t)NEXP * NDIM * KDIM];
__device__ __align__(1024) __half g_h[(size_t)M_TOT * NDIM];        // fp16(gelu)
__device__ __align__(1024) float  g_y[(size_t)M_TOT * HIDDEN];

// ---------------------------------------------------------------- helpers
__device__ __forceinline__ uint32_t smem_u32(const void* p) {
    uint32_t a;
    asm("{ .reg .u64 t; cvta.to.shared.u64 t, %1; cvt.u32.u64 %0, t; }"
        : "=r"(a) : "l"(p));
    return a;
}
__device__ __forceinline__ uint32_t sw128(uint32_t off) {
    return off ^ ((off >> 3) & 0x70);
}
__device__ __forceinline__ void cp16(uint32_t dst, const void* src) {
    asm volatile("cp.async.cg.shared.global [%0], [%1], 16;"
                 :: "r"(dst), "l"(src));
}
__device__ __forceinline__ void cp_commit() {
    asm volatile("cp.async.commit_group;");
}
template <int N>
__device__ __forceinline__ void cp_wait() {
    asm volatile("cp.async.wait_group %0;" :: "n"(N));
}
__device__ __forceinline__ void ldsm4(uint32_t* r, uint32_t addr) {
    asm volatile("ldmatrix.sync.aligned.m8n8.x4.shared.b16 {%0,%1,%2,%3}, [%4];"
                 : "=r"(r[0]), "=r"(r[1]), "=r"(r[2]), "=r"(r[3]) : "r"(addr));
}
__device__ __forceinline__ void mma_f16(float* c, const uint32_t* a,
                                        const uint32_t* b) {
    asm volatile(
        "mma.sync.aligned.m16n8k16.row.col.f32.f16.f16.f32 "
        "{%0,%1,%2,%3},{%4,%5,%6,%7},{%8,%9},{%0,%1,%2,%3};"
        : "+f"(c[0]), "+f"(c[1]), "+f"(c[2]), "+f"(c[3])
        : "r"(a[0]), "r"(a[1]), "r"(a[2]), "r"(a[3]), "r"(b[0]), "r"(b[1]));
}

// ---------------------------------------------------------------- GEMM
// C[r,n] = (1/32) * sum_k A[r,k] * Wq[e,n,k]   (A fp16, Wq = fp16(32*w))
template <bool GELU>
__global__ void __launch_bounds__(256, 2)
gemm_f16(const __half* __restrict__ A, const __half* __restrict__ Wq,
         __half* __restrict__ out_h, float* __restrict__ out_f32) {
    extern __shared__ __align__(1024) char smem[];
    const uint32_t sb = smem_u32(smem);
    const int tid  = threadIdx.x;
    const int lane = tid & 31;
    const int w    = tid >> 5;
    const int wm   = w & 1;       // M half (64 rows)
    const int wn   = w >> 1;      // N quarter (32 cols)
    const int grow0 = blockIdx.y * BM;
    const int gcol0 = blockIdx.x * BN;
    const int e     = grow0 / CAP;

    // ---- loader: 8 x 16B per thread per stage; warp covers 4 full 128B lines
    const int ltile = tid >> 7;          // 0 = A, 1 = B
    const int lc    = tid & 7;           // 16B chunk within 128B row
    const int lr0   = (tid & 127) >> 3;  // row 0..15 (then +16 per sub-iter)
    // rows lr0+16i share low 3 bits -> swizzle term constant; +i*2048 bytes
    const uint32_t soff0 = (uint32_t)ltile * TILE_BYTES +
                           sw128((uint32_t)lr0 * 128 + lc * 16);
    const __half* gsrc = (ltile == 0)
        ? A  + (size_t)(grow0 + lr0) * KDIM + lc * 8
        : Wq + ((size_t)e * NDIM + gcol0 + lr0) * KDIM + lc * 8;

    auto load_stage = [&](int it) {
        if (it < NITER) {
            const uint32_t dst = sb + (uint32_t)(it % NS) * STAGE_BYTES + soff0;
            const __half* src = gsrc + it * BK;
#pragma unroll
            for (int i = 0; i < 8; i++)
                cp16(dst + i * 2048, src + (size_t)i * 16 * KDIM);
        }
        cp_commit();
    };

    // ---- ldmatrix per-lane offsets (128B rows)
    const int ar  = lane & 15;
    const int akh = lane >> 4;
    const uint32_t aoff = sw128((uint32_t)ar * 128 + akh * 16);
    const int brn = lane & 7;
    const int bh  = (lane >> 3) & 1;
    const int bgs = lane >> 4;
    const int nrow0 = wn * 32 + bgs * 8 + brn;
    const uint32_t boff0 = sw128((uint32_t)nrow0 * 128 + bh * 16);
    const uint32_t boff1 = sw128((uint32_t)(nrow0 + 16) * 128 + bh * 16);

    float acc[4][4][4];
#pragma unroll
    for (int i = 0; i < 4; i++)
#pragma unroll
        for (int j = 0; j < 4; j++)
#pragma unroll
            for (int k = 0; k < 4; k++) acc[i][j][k] = 0.f;

    load_stage(0);
    load_stage(1);

    for (int it = 0; it < NITER; it++) {
        cp_wait<1>();
        __syncthreads();
        load_stage(it + 2);

        const uint32_t base = sb + (uint32_t)(it % NS) * STAGE_BYTES;
#pragma unroll
        for (int kk = 0; kk < 4; kk++) {
            const uint32_t kx = (uint32_t)kk << 5;   // 32B per k16 chunk
            uint32_t bF[4][2];
            {
                uint32_t t0[4], t1[4];
                ldsm4(t0, base + OFF_B + (boff0 ^ kx));
                bF[0][0] = t0[0]; bF[0][1] = t0[1];
                bF[1][0] = t0[2]; bF[1][1] = t0[3];
                ldsm4(t1, base + OFF_B + (boff1 ^ kx));
                bF[2][0] = t1[0]; bF[2][1] = t1[1];
                bF[3][0] = t1[2]; bF[3][1] = t1[3];
            }
            const uint32_t aaddr = base + OFF_A + wm * 8192 + (aoff ^ kx);
#pragma unroll
            for (int mi = 0; mi < 4; mi++) {
                uint32_t aF[4];
                ldsm4(aF, aaddr + mi * 2048);
#pragma unroll
                for (int g = 0; g < 4; g++)
                    mma_f16(acc[mi][g], aF, bF[g]);
            }
        }
    }

    // ---------------- epilogue
    const int r_in = lane >> 2;
    const int c_in = (lane & 3) * 2;
#pragma unroll
    for (int mi = 0; mi < 4; mi++) {
#pragma unroll
        for (int g = 0; g < 4; g++) {
            const int row0 = grow0 + wm * 64 + mi * 16 + r_in;
            const int col  = gcol0 + wn * 32 + g * 8 + c_in;
#pragma unroll
            for (int half = 0; half < 2; half++) {
                const int row = row0 + half * 8;
                float v0 = acc[mi][g][half * 2 + 0] * WSCALEINV;
                float v1 = acc[mi][g][half * 2 + 1] * WSCALEINV;
                const size_t off = (size_t)row * NDIM + col;
                if (GELU) {
                    v0 = 0.5f * v0 * (1.0f + erff(v0 * 0.70710678118654752f));
                    v1 = 0.5f * v1 * (1.0f + erff(v1 * 0.70710678118654752f));
                    *(__half2*)(out_h + off) =
                        __halves2half2(__float2half(v0), __float2half(v1));
                } else {
                    *(float2*)(out_f32 + off) = make_float2(v0, v1);
                }
            }
        }
    }
}

// ---------------------------------------------------------------- conversions
// Weights: wq = fp16(32*w).
__global__ void quant_w_kernel(const float* __restrict__ in,
                               __half* __restrict__ q) {
    const size_t i = (size_t)blockIdx.x * blockDim.x + threadIdx.x; // over n/4
    float4 v = ((const float4*)in)[i];
    ((__half2*)q)[2 * i]     = __halves2half2(__float2half(v.x * WSCALE),
                                              __float2half(v.y * WSCALE));
    ((__half2*)q)[2 * i + 1] = __halves2half2(__float2half(v.z * WSCALE),
                                              __float2half(v.w * WSCALE));
}

// x -> fp16, scattered to expert-sorted rows.
__global__ void scatter_q_kernel(const float* __restrict__ x,
                                 const int* __restrict__ scat,
                                 __half* __restrict__ q) {
    const int p = blockIdx.x;                 // [0, M_TOT)
    const int d = scat[p];
    const float4* src = (const float4*)(x + (size_t)(p >> 1) * HIDDEN);
    __half2* dq = (__half2*)(q + (size_t)d * HIDDEN);
    for (int c = threadIdx.x; c < HIDDEN / 4; c += blockDim.x) {
        float4 v = src[c];
        dq[2 * c]     = __halves2half2(__float2half(v.x), __float2half(v.y));
        dq[2 * c + 1] = __halves2half2(__float2half(v.z), __float2half(v.w));
    }
}

__global__ void combine_kernel(const int* __restrict__ scat, float* __restrict__ out) {
    const int idx = blockIdx.x * blockDim.x + threadIdx.x;   // NTOK * HIDDEN/4
    const int t  = idx / (HIDDEN / 4);
    const int c4 = (idx % (HIDDEN / 4)) * 4;
    const int s0 = scat[t * TOPK + 0];
    const int s1 = scat[t * TOPK + 1];
    float4 v0 = *(const float4*)(g_y + (size_t)s0 * HIDDEN + c4);
    float4 v1 = *(const float4*)(g_y + (size_t)s1 * HIDDEN + c4);
    *(float4*)(out + (size_t)t * HIDDEN + c4) =
        make_float4(v0.x + v1.x, v0.y + v1.y, v0.z + v1.z, v0.w + v1.w);
}

// ---------------------------------------------------------------- host
extern "C" void kernel_launch(void* const* d_in, const int* in_sizes, int n_in,
                              void* d_out, int out_size) {
    const float* x    = (const float*)d_in[0];
    const float* w1   = (const float*)d_in[1];
    const float* w2   = (const float*)d_in[2];
    const int*   scat = (const int*)d_in[3];
    float* out = (float*)d_out;

    void *xq, *w1q, *w2q, *hb, *yb;
    cudaGetSymbolAddress(&xq, g_xq);
    cudaGetSymbolAddress(&w1q, g_w1q);
    cudaGetSymbolAddress(&w2q, g_w2q);
    cudaGetSymbolAddress(&hb, g_h);
    cudaGetSymbolAddress(&yb, g_y);

    cudaFuncSetAttribute(gemm_f16<true>,  cudaFuncAttributeMaxDynamicSharedMemorySize,
                         (int)SMEM_SZ);
    cudaFuncSetAttribute(gemm_f16<false>, cudaFuncAttributeMaxDynamicSharedMemorySize,
                         (int)SMEM_SZ);

    // conversions
    quant_w_kernel<<<(NEXP * NDIM * KDIM) / (256 * 4), 256>>>(w1, (__half*)w1q);
    quant_w_kernel<<<(NEXP * NDIM * KDIM) / (256 * 4), 256>>>(w2, (__half*)w2q);
    scatter_q_kernel<<<M_TOT, 256>>>(x, scat, (__half*)xq);

    // fc1: x @ w1^T -> gelu -> h (fp16)
    gemm_f16<true><<<dim3(NDIM / BN, M_TOT / BM), 256, SMEM_SZ>>>(
        (const __half*)xq, (const __half*)w1q, (__half*)hb, nullptr);

    // fc2: h @ w2^T -> y (f32)
    gemm_f16<false><<<dim3(HIDDEN / BN, M_TOT / BM), 256, SMEM_SZ>>>(
        (const __half*)hb, (const __half*)w2q, nullptr, (float*)yb);

    combine_kernel<<<(NTOK * (HIDDEN / 4)) / 256, 256>>>(scat, out);
}

// round 10
// speedup vs baseline: 7.1584x; 1.0645x over previous
#include <cuda_runtime.h>
#include <cuda_fp16.h>
#include <math.h>
#include <stdint.h>

// ---------------------------------------------------------------- constants
#define NTOK   8192
#define HIDDEN 2048
#define NEXP   8
#define TOPK   2
#define M_TOT  (NTOK * TOPK)      // 16384
#define CAP    (M_TOT / NEXP)     // 2048
#define KDIM   2048
#define NDIM   2048

constexpr int BM = 128, BN = 128, BK = 64;
constexpr int NS = 3;                          // pipeline ring slots
constexpr int NITER = KDIM / BK;               // 32
constexpr uint32_t TILE_BYTES  = 128 * 128;    // 16 KB: 128 rows x 64 fp16 (128B rows)
constexpr uint32_t OFF_A = 0;
constexpr uint32_t OFF_B = TILE_BYTES;
constexpr uint32_t STAGE_BYTES = 2 * TILE_BYTES;   // 32 KB
constexpr uint32_t SMEM_SZ     = NS * STAGE_BYTES; // 96 KB

constexpr float WSCALE    = 32.0f;             // weights pre-scaled into fp16 range
constexpr float WSCALEINV = 1.0f / 32.0f;

// ---------------------------------------------------------------- scratch
__device__ __align__(1024) __half g_xq[(size_t)M_TOT * KDIM];       // fp16(x), scattered
__device__ __align__(1024) __half g_w1q[(size_t)NEXP * NDIM * KDIM];
__device__ __align__(1024) __half g_w2q[(size_t)NEXP * NDIM * KDIM];
__device__ __align__(1024) __half g_h[(size_t)M_TOT * NDIM];        // fp16(gelu)
__device__ __align__(1024) float  g_y[(size_t)M_TOT * HIDDEN];

// ---------------------------------------------------------------- helpers
__device__ __forceinline__ uint32_t smem_u32(const void* p) {
    uint32_t a;
    asm("{ .reg .u64 t; cvta.to.shared.u64 t, %1; cvt.u32.u64 %0, t; }"
        : "=r"(a) : "l"(p));
    return a;
}
__device__ __forceinline__ uint32_t sw128(uint32_t off) {
    return off ^ ((off >> 3) & 0x70);
}
__device__ __forceinline__ void cp16(uint32_t dst, const void* src) {
    asm volatile("cp.async.cg.shared.global [%0], [%1], 16;"
                 :: "r"(dst), "l"(src));
}
__device__ __forceinline__ void cp_commit() {
    asm volatile("cp.async.commit_group;");
}
template <int N>
__device__ __forceinline__ void cp_wait() {
    asm volatile("cp.async.wait_group %0;" :: "n"(N));
}
__device__ __forceinline__ void ldsm4(uint32_t* r, uint32_t addr) {
    asm volatile("ldmatrix.sync.aligned.m8n8.x4.shared.b16 {%0,%1,%2,%3}, [%4];"
                 : "=r"(r[0]), "=r"(r[1]), "=r"(r[2]), "=r"(r[3]) : "r"(addr));
}
__device__ __forceinline__ void mma_f16(float* c, const uint32_t* a,
                                        const uint32_t* b) {
    asm volatile(
        "mma.sync.aligned.m16n8k16.row.col.f32.f16.f16.f32 "
        "{%0,%1,%2,%3},{%4,%5,%6,%7},{%8,%9},{%0,%1,%2,%3};"
        : "+f"(c[0]), "+f"(c[1]), "+f"(c[2]), "+f"(c[3])
        : "r"(a[0]), "r"(a[1]), "r"(a[2]), "r"(a[3]), "r"(b[0]), "r"(b[1]));
}

// ---------------------------------------------------------------- GEMM
// C[r,n] = (1/32) * sum_k A[r,k] * Wq[e,n,k]   (A fp16, Wq = fp16(32*w))
// 128 threads (4 warps, 2x2), warp tile 64x64 -> minimal smem crossbar traffic.
template <bool GELU>
__global__ void __launch_bounds__(128, 2)
gemm_f16(const __half* __restrict__ A, const __half* __restrict__ Wq,
         __half* __restrict__ out_h, float* __restrict__ out_f32) {
    extern __shared__ __align__(1024) char smem[];
    const uint32_t sb = smem_u32(smem);
    const int tid  = threadIdx.x;
    const int lane = tid & 31;
    const int w    = tid >> 5;
    const int wm   = w & 1;       // M half (64 rows)
    const int wn   = w >> 1;      // N half (64 cols)
    const int grow0 = blockIdx.y * BM;
    const int gcol0 = blockIdx.x * BN;
    const int e     = grow0 / CAP;

    // ---- loader: 16 x 16B per thread per stage; 8 threads cover one 128B row
    const int ltile = tid >> 6;          // 0 = A, 1 = B
    const int lc    = tid & 7;           // 16B chunk within 128B row
    const int lr0   = (tid & 63) >> 3;   // row 0..7 (then +8 per sub-iter)
    // rows lr0+8i share low 3 bits -> swizzle term constant; +i*1024 bytes
    const uint32_t soff0 = (uint32_t)ltile * TILE_BYTES +
                           sw128((uint32_t)lr0 * 128 + lc * 16);
    const __half* gsrc = (ltile == 0)
        ? A  + (size_t)(grow0 + lr0) * KDIM + lc * 8
        : Wq + ((size_t)e * NDIM + gcol0 + lr0) * KDIM + lc * 8;

    auto load_stage = [&](int it) {
        if (it < NITER) {
            const uint32_t dst = sb + (uint32_t)(it % NS) * STAGE_BYTES + soff0;
            const __half* src = gsrc + it * BK;
#pragma unroll
            for (int i = 0; i < 16; i++)
                cp16(dst + i * 1024, src + (size_t)i * 8 * KDIM);
        }
        cp_commit();
    };

    // ---- ldmatrix per-lane offsets (128B rows)
    const int ar  = lane & 15;
    const int akh = lane >> 4;
    const uint32_t aoff = sw128((uint32_t)ar * 128 + akh * 16);
    const int brn = lane & 7;
    const int bh  = (lane >> 3) & 1;
    const int bgs = lane >> 4;
    uint32_t boff[4];
#pragma unroll
    for (int j = 0; j < 4; j++) {
        const int nrow = wn * 64 + j * 16 + bgs * 8 + brn;
        boff[j] = sw128((uint32_t)nrow * 128 + bh * 16);
    }

    float acc[4][8][4];
#pragma unroll
    for (int i = 0; i < 4; i++)
#pragma unroll
        for (int j = 0; j < 8; j++)
#pragma unroll
            for (int k = 0; k < 4; k++) acc[i][j][k] = 0.f;

    load_stage(0);
    load_stage(1);

    for (int it = 0; it < NITER; it++) {
        cp_wait<1>();
        __syncthreads();
        load_stage(it + 2);

        const uint32_t base = sb + (uint32_t)(it % NS) * STAGE_BYTES;
#pragma unroll
        for (int kk = 0; kk < 4; kk++) {
            const uint32_t kx = (uint32_t)kk << 5;   // 32B per k16 chunk
            uint32_t bF[8][2];
#pragma unroll
            for (int j = 0; j < 4; j++) {
                uint32_t t[4];
                ldsm4(t, base + OFF_B + (boff[j] ^ kx));
                bF[2 * j][0]     = t[0]; bF[2 * j][1]     = t[1];
                bF[2 * j + 1][0] = t[2]; bF[2 * j + 1][1] = t[3];
            }
            const uint32_t aaddr = base + OFF_A + wm * 8192 + (aoff ^ kx);
#pragma unroll
            for (int mi = 0; mi < 4; mi++) {
                uint32_t aF[4];
                ldsm4(aF, aaddr + mi * 2048);
#pragma unroll
                for (int g = 0; g < 8; g++)
                    mma_f16(acc[mi][g], aF, bF[g]);
            }
        }
    }

    // ---------------- epilogue
    const int r_in = lane >> 2;
    const int c_in = (lane & 3) * 2;
#pragma unroll
    for (int mi = 0; mi < 4; mi++) {
#pragma unroll
        for (int g = 0; g < 8; g++) {
            const int row0 = grow0 + wm * 64 + mi * 16 + r_in;
            const int col  = gcol0 + wn * 64 + g * 8 + c_in;
#pragma unroll
            for (int half = 0; half < 2; half++) {
                const int row = row0 + half * 8;
                float v0 = acc[mi][g][half * 2 + 0] * WSCALEINV;
                float v1 = acc[mi][g][half * 2 + 1] * WSCALEINV;
                const size_t off = (size_t)row * NDIM + col;
                if (GELU) {
                    v0 = 0.5f * v0 * (1.0f + erff(v0 * 0.70710678118654752f));
                    v1 = 0.5f * v1 * (1.0f + erff(v1 * 0.70710678118654752f));
                    *(__half2*)(out_h + off) =
                        __halves2half2(__float2half(v0), __float2half(v1));
                } else {
                    *(float2*)(out_f32 + off) = make_float2(v0, v1);
                }
            }
        }
    }
}

// ---------------------------------------------------------------- conversions
// Weights: wq = fp16(32*w).
__global__ void quant_w_kernel(const float* __restrict__ in,
                               __half* __restrict__ q) {
    const size_t i = (size_t)blockIdx.x * blockDim.x + threadIdx.x; // over n/4
    float4 v = ((const float4*)in)[i];
    ((__half2*)q)[2 * i]     = __halves2half2(__float2half(v.x * WSCALE),
                                              __float2half(v.y * WSCALE));
    ((__half2*)q)[2 * i + 1] = __halves2half2(__float2half(v.z * WSCALE),
                                              __float2half(v.w * WSCALE));
}

// x -> fp16, scattered to expert-sorted rows.
__global__ void scatter_q_kernel(const float* __restrict__ x,
                                 const int* __restrict__ scat,
                                 __half* __restrict__ q) {
    const int p = blockIdx.x;                 // [0, M_TOT)
    const int d = scat[p];
    const float4* src = (const float4*)(x + (size_t)(p >> 1) * HIDDEN);
    __half2* dq = (__half2*)(q + (size_t)d * HIDDEN);
    for (int c = threadIdx.x; c < HIDDEN / 4; c += blockDim.x) {
        float4 v = src[c];
        dq[2 * c]     = __halves2half2(__float2half(v.x), __float2half(v.y));
        dq[2 * c + 1] = __halves2half2(__float2half(v.z), __float2half(v.w));
    }
}

__global__ void combine_kernel(const int* __restrict__ scat, float* __restrict__ out) {
    const int idx = blockIdx.x * blockDim.x + threadIdx.x;   // NTOK * HIDDEN/4
    const int t  = idx / (HIDDEN / 4);
    const int c4 = (idx % (HIDDEN / 4)) * 4;
    const int s0 = scat[t * TOPK + 0];
    const int s1 = scat[t * TOPK + 1];
    float4 v0 = *(const float4*)(g_y + (size_t)s0 * HIDDEN + c4);
    float4 v1 = *(const float4*)(g_y + (size_t)s1 * HIDDEN + c4);
    *(float4*)(out + (size_t)t * HIDDEN + c4) =
        make_float4(v0.x + v1.x, v0.y + v1.y, v0.z + v1.z, v0.w + v1.w);
}

// ---------------------------------------------------------------- host
extern "C" void kernel_launch(void* const* d_in, const int* in_sizes, int n_in,
                              void* d_out, int out_size) {
    const float* x    = (const float*)d_in[0];
    const float* w1   = (const float*)d_in[1];
    const float* w2   = (const float*)d_in[2];
    const int*   scat = (const int*)d_in[3];
    float* out = (float*)d_out;

    void *xq, *w1q, *w2q, *hb, *yb;
    cudaGetSymbolAddress(&xq, g_xq);
    cudaGetSymbolAddress(&w1q, g_w1q);
    cudaGetSymbolAddress(&w2q, g_w2q);
    cudaGetSymbolAddress(&hb, g_h);
    cudaGetSymbolAddress(&yb, g_y);

    cudaFuncSetAttribute(gemm_f16<true>,  cudaFuncAttributeMaxDynamicSharedMemorySize,
                         (int)SMEM_SZ);
    cudaFuncSetAttribute(gemm_f16<false>, cudaFuncAttributeMaxDynamicSharedMemorySize,
                         (int)SMEM_SZ);

    // conversions
    quant_w_kernel<<<(NEXP * NDIM * KDIM) / (256 * 4), 256>>>(w1, (__half*)w1q);
    quant_w_kernel<<<(NEXP * NDIM * KDIM) / (256 * 4), 256>>>(w2, (__half*)w2q);
    scatter_q_kernel<<<M_TOT, 256>>>(x, scat, (__half*)xq);

    // fc1: x @ w1^T -> gelu -> h (fp16)
    gemm_f16<true><<<dim3(NDIM / BN, M_TOT / BM), 128, SMEM_SZ>>>(
        (const __half*)xq, (const __half*)w1q, (__half*)hb, nullptr);

    // fc2: h @ w2^T -> y (f32)
    gemm_f16<false><<<dim3(HIDDEN / BN, M_TOT / BM), 128, SMEM_SZ>>>(
        (const __half*)hb, (const __half*)w2q, nullptr, (float*)yb);

    combine_kernel<<<(NTOK * (HIDDEN / 4)) / 256, 256>>>(scat, out);
}

// round 11
// speedup vs baseline: 7.2680x; 1.0153x over previous
#include <cuda_runtime.h>
#include <cuda_fp16.h>
#include <math.h>
#include <stdint.h>

// ---------------------------------------------------------------- constants
#define NTOK   8192
#define HIDDEN 2048
#define NEXP   8
#define TOPK   2
#define M_TOT  (NTOK * TOPK)      // 16384
#define CAP    (M_TOT / NEXP)     // 2048
#define KDIM   2048
#define NDIM   2048

constexpr int BM = 128, BN = 128, BK = 64;
constexpr int NS = 3;                          // pipeline ring slots
constexpr int NITER = KDIM / BK;               // 32
constexpr uint32_t TILE_BYTES  = 128 * 128;    // 16 KB: 128 rows x 64 fp16 (128B rows)
constexpr uint32_t OFF_A = 0;
constexpr uint32_t OFF_B = TILE_BYTES;
constexpr uint32_t STAGE_BYTES = 2 * TILE_BYTES;   // 32 KB
constexpr uint32_t SMEM_SZ     = NS * STAGE_BYTES; // 96 KB

constexpr float WSCALE    = 32.0f;             // weights pre-scaled into fp16 range
constexpr float WSCALEINV = 1.0f / 32.0f;

// ---------------------------------------------------------------- scratch
__device__ __align__(1024) __half g_xq[(size_t)M_TOT * KDIM];       // fp16(x), scattered
__device__ __align__(1024) __half g_w1q[(size_t)NEXP * NDIM * KDIM];
__device__ __align__(1024) __half g_w2q[(size_t)NEXP * NDIM * KDIM];
__device__ __align__(1024) __half g_h[(size_t)M_TOT * NDIM];        // fp16(gelu)
__device__ __align__(1024) float  g_y[(size_t)M_TOT * HIDDEN];

// ---------------------------------------------------------------- helpers
__device__ __forceinline__ uint32_t smem_u32(const void* p) {
    uint32_t a;
    asm("{ .reg .u64 t; cvta.to.shared.u64 t, %1; cvt.u32.u64 %0, t; }"
        : "=r"(a) : "l"(p));
    return a;
}
__device__ __forceinline__ uint32_t sw128(uint32_t off) {
    return off ^ ((off >> 3) & 0x70);
}
__device__ __forceinline__ void cp16(uint32_t dst, const void* src) {
    asm volatile("cp.async.cg.shared.global [%0], [%1], 16;"
                 :: "r"(dst), "l"(src));
}
__device__ __forceinline__ void cp_commit() {
    asm volatile("cp.async.commit_group;");
}
template <int N>
__device__ __forceinline__ void cp_wait() {
    asm volatile("cp.async.wait_group %0;" :: "n"(N));
}
__device__ __forceinline__ void ldsm4(uint32_t* r, uint32_t addr) {
    asm volatile("ldmatrix.sync.aligned.m8n8.x4.shared.b16 {%0,%1,%2,%3}, [%4];"
                 : "=r"(r[0]), "=r"(r[1]), "=r"(r[2]), "=r"(r[3]) : "r"(addr));
}
__device__ __forceinline__ void mma_f16(float* c, const uint32_t* a,
                                        const uint32_t* b) {
    asm volatile(
        "mma.sync.aligned.m16n8k16.row.col.f32.f16.f16.f32 "
        "{%0,%1,%2,%3},{%4,%5,%6,%7},{%8,%9},{%0,%1,%2,%3};"
        : "+f"(c[0]), "+f"(c[1]), "+f"(c[2]), "+f"(c[3])
        : "r"(a[0]), "r"(a[1]), "r"(a[2]), "r"(a[3]), "r"(b[0]), "r"(b[1]));
}

// ---------------------------------------------------------------- GEMM
// C[r,n] = (1/32) * sum_k A[r,k] * Wq[e,n,k]   (A fp16, Wq = fp16(32*w))
// 128 threads (4 warps, 2x2), warp tile 64x64; A/B fragments software-pipelined
// (double-buffered in registers) so every ldsm is issued one MMA-group early.
template <bool GELU>
__global__ void __launch_bounds__(128, 2)
gemm_f16(const __half* __restrict__ A, const __half* __restrict__ Wq,
         __half* __restrict__ out_h, float* __restrict__ out_f32) {
    extern __shared__ __align__(1024) char smem[];
    const uint32_t sb = smem_u32(smem);
    const int tid  = threadIdx.x;
    const int lane = tid & 31;
    const int w    = tid >> 5;
    const int wm   = w & 1;       // M half (64 rows)
    const int wn   = w >> 1;      // N half (64 cols)
    const int grow0 = blockIdx.y * BM;
    const int gcol0 = blockIdx.x * BN;
    const int e     = grow0 / CAP;

    // ---- loader: 16 x 16B per thread per stage; 8 threads cover one 128B row
    const int ltile = tid >> 6;          // 0 = A, 1 = B
    const int lc    = tid & 7;           // 16B chunk within 128B row
    const int lr0   = (tid & 63) >> 3;   // row 0..7 (then +8 per sub-iter)
    const uint32_t soff0 = (uint32_t)ltile * TILE_BYTES +
                           sw128((uint32_t)lr0 * 128 + lc * 16);
    const __half* gsrc = (ltile == 0)
        ? A  + (size_t)(grow0 + lr0) * KDIM + lc * 8
        : Wq + ((size_t)e * NDIM + gcol0 + lr0) * KDIM + lc * 8;

    auto load_stage = [&](int it) {
        if (it < NITER) {
            const uint32_t dst = sb + (uint32_t)(it % NS) * STAGE_BYTES + soff0;
            const __half* src = gsrc + it * BK;
#pragma unroll
            for (int i = 0; i < 16; i++)
                cp16(dst + i * 1024, src + (size_t)i * 8 * KDIM);
        }
        cp_commit();
    };

    // ---- ldmatrix per-lane offsets (128B rows)
    const int ar  = lane & 15;
    const int akh = lane >> 4;
    const uint32_t aoff = sw128((uint32_t)ar * 128 + akh * 16);
    const int brn = lane & 7;
    const int bh  = (lane >> 3) & 1;
    const int bgs = lane >> 4;
    uint32_t boff[4];
#pragma unroll
    for (int j = 0; j < 4; j++) {
        const int nrow = wn * 64 + j * 16 + bgs * 8 + brn;
        boff[j] = sw128((uint32_t)nrow * 128 + bh * 16);
    }

    float acc[4][8][4];
#pragma unroll
    for (int i = 0; i < 4; i++)
#pragma unroll
        for (int j = 0; j < 8; j++)
#pragma unroll
            for (int k = 0; k < 4; k++) acc[i][j][k] = 0.f;

    load_stage(0);
    load_stage(1);

    for (int it = 0; it < NITER; it++) {
        cp_wait<1>();
        __syncthreads();
        const uint32_t base = sb + (uint32_t)(it % NS) * STAGE_BYTES;
        const uint32_t ab = base + OFF_A + wm * 8192;
        const uint32_t bb = base + OFF_B;

        uint32_t bF[2][8][2];   // double-buffered B fragments (per k16)
        uint32_t aF[2][4];      // double-buffered A fragments (per mi)

        // prime kk=0 fragments before issuing the long cp.async burst
#pragma unroll
        for (int j = 0; j < 4; j++) {
            uint32_t t[4];
            ldsm4(t, bb + boff[j]);
            bF[0][2 * j][0] = t[0]; bF[0][2 * j][1] = t[1];
            bF[0][2 * j + 1][0] = t[2]; bF[0][2 * j + 1][1] = t[3];
        }
        ldsm4(aF[0], ab + aoff);

        load_stage(it + 2);

#pragma unroll
        for (int kk = 0; kk < 4; kk++) {
            const int cb = kk & 1;
            const uint32_t kx = (uint32_t)kk << 5;
#pragma unroll
            for (int mi = 0; mi < 4; mi++) {
                const int ca = (kk * 4 + mi) & 1;
                // prefetch next fragments one MMA-group ahead
                if (mi < 3) {
                    ldsm4(aF[ca ^ 1], ab + (aoff ^ kx) + (mi + 1) * 2048);
                } else if (kk < 3) {
                    const uint32_t kx2 = (uint32_t)(kk + 1) << 5;
#pragma unroll
                    for (int j = 0; j < 4; j++) {
                        uint32_t t[4];
                        ldsm4(t, bb + (boff[j] ^ kx2));
                        bF[cb ^ 1][2 * j][0] = t[0]; bF[cb ^ 1][2 * j][1] = t[1];
                        bF[cb ^ 1][2 * j + 1][0] = t[2]; bF[cb ^ 1][2 * j + 1][1] = t[3];
                    }
                    ldsm4(aF[ca ^ 1], ab + (aoff ^ kx2));
                }
#pragma unroll
                for (int g = 0; g < 8; g++)
                    mma_f16(acc[mi][g], aF[ca], bF[cb][g]);
            }
        }
    }

    // ---------------- epilogue
    const int r_in = lane >> 2;
    const int c_in = (lane & 3) * 2;
#pragma unroll
    for (int mi = 0; mi < 4; mi++) {
#pragma unroll
        for (int g = 0; g < 8; g++) {
            const int row0 = grow0 + wm * 64 + mi * 16 + r_in;
            const int col  = gcol0 + wn * 64 + g * 8 + c_in;
#pragma unroll
            for (int half = 0; half < 2; half++) {
                const int row = row0 + half * 8;
                float v0 = acc[mi][g][half * 2 + 0] * WSCALEINV;
                float v1 = acc[mi][g][half * 2 + 1] * WSCALEINV;
                const size_t off = (size_t)row * NDIM + col;
                if (GELU) {
                    v0 = 0.5f * v0 * (1.0f + erff(v0 * 0.70710678118654752f));
                    v1 = 0.5f * v1 * (1.0f + erff(v1 * 0.70710678118654752f));
                    *(__half2*)(out_h + off) =
                        __halves2half2(__float2half(v0), __float2half(v1));
                } else {
                    *(float2*)(out_f32 + off) = make_float2(v0, v1);
                }
            }
        }
    }
}

// ---------------------------------------------------------------- conversions
// Weights: wq = fp16(32*w).
__global__ void quant_w_kernel(const float* __restrict__ in,
                               __half* __restrict__ q) {
    const size_t i = (size_t)blockIdx.x * blockDim.x + threadIdx.x; // over n/4
    float4 v = ((const float4*)in)[i];
    ((__half2*)q)[2 * i]     = __halves2half2(__float2half(v.x * WSCALE),
                                              __float2half(v.y * WSCALE));
    ((__half2*)q)[2 * i + 1] = __halves2half2(__float2half(v.z * WSCALE),
                                              __float2half(v.w * WSCALE));
}

// x -> fp16, scattered to expert-sorted rows.
__global__ void scatter_q_kernel(const float* __restrict__ x,
                                 const int* __restrict__ scat,
                                 __half* __restrict__ q) {
    const int p = blockIdx.x;                 // [0, M_TOT)
    const int d = scat[p];
    const float4* src = (const float4*)(x + (size_t)(p >> 1) * HIDDEN);
    __half2* dq = (__half2*)(q + (size_t)d * HIDDEN);
    for (int c = threadIdx.x; c < HIDDEN / 4; c += blockDim.x) {
        float4 v = src[c];
        dq[2 * c]     = __halves2half2(__float2half(v.x), __float2half(v.y));
        dq[2 * c + 1] = __halves2half2(__float2half(v.z), __float2half(v.w));
    }
}

__global__ void combine_kernel(const int* __restrict__ scat, float* __restrict__ out) {
    const int idx = blockIdx.x * blockDim.x + threadIdx.x;   // NTOK * HIDDEN/4
    const int t  = idx / (HIDDEN / 4);
    const int c4 = (idx % (HIDDEN / 4)) * 4;
    const int s0 = scat[t * TOPK + 0];
    const int s1 = scat[t * TOPK + 1];
    float4 v0 = *(const float4*)(g_y + (size_t)s0 * HIDDEN + c4);
    float4 v1 = *(const float4*)(g_y + (size_t)s1 * HIDDEN + c4);
    *(float4*)(out + (size_t)t * HIDDEN + c4) =
        make_float4(v0.x + v1.x, v0.y + v1.y, v0.z + v1.z, v0.w + v1.w);
}

// ---------------------------------------------------------------- host
extern "C" void kernel_launch(void* const* d_in, const int* in_sizes, int n_in,
                              void* d_out, int out_size) {
    const float* x    = (const float*)d_in[0];
    const float* w1   = (const float*)d_in[1];
    const float* w2   = (const float*)d_in[2];
    const int*   scat = (const int*)d_in[3];
    float* out = (float*)d_out;

    void *xq, *w1q, *w2q, *hb, *yb;
    cudaGetSymbolAddress(&xq, g_xq);
    cudaGetSymbolAddress(&w1q, g_w1q);
    cudaGetSymbolAddress(&w2q, g_w2q);
    cudaGetSymbolAddress(&hb, g_h);
    cudaGetSymbolAddress(&yb, g_y);

    cudaFuncSetAttribute(gemm_f16<true>,  cudaFuncAttributeMaxDynamicSharedMemorySize,
                         (int)SMEM_SZ);
    cudaFuncSetAttribute(gemm_f16<false>, cudaFuncAttributeMaxDynamicSharedMemorySize,
                         (int)SMEM_SZ);

    // conversions
    quant_w_kernel<<<(NEXP * NDIM * KDIM) / (256 * 4), 256>>>(w1, (__half*)w1q);
    quant_w_kernel<<<(NEXP * NDIM * KDIM) / (256 * 4), 256>>>(w2, (__half*)w2q);
    scatter_q_kernel<<<M_TOT, 256>>>(x, scat, (__half*)xq);

    // fc1: x @ w1^T -> gelu -> h (fp16)
    gemm_f16<true><<<dim3(NDIM / BN, M_TOT / BM), 128, SMEM_SZ>>>(
        (const __half*)xq, (const __half*)w1q, (__half*)hb, nullptr);

    // fc2: h @ w2^T -> y (f32)
    gemm_f16<false><<<dim3(HIDDEN / BN, M_TOT / BM), 128, SMEM_SZ>>>(
        (const __half*)hb, (const __half*)w2q, nullptr, (float*)yb);

    combine_kernel<<<(NTOK * (HIDDEN / 4)) / 256, 256>>>(scat, out);
}